// round 12
// baseline (speedup 1.0000x reference)
#include <cuda_runtime.h>
#include <cuda_bf16.h>
#include <stdint.h>
#include <math.h>

#define NN 10000
#define NE 320000
#define DD 256
#define NL 3

typedef __nv_bfloat16 bf16;
typedef unsigned int uint;

// ---------------- scratch -----------------------------------------------------
__device__ bf16  g_xh[NN * DD], g_xl[NN * DD];          // x hi/lo, reused as agg hi/lo
__device__ bf16  g_hhA[NN * DD], g_hlA[NN * DD];
__device__ bf16  g_hhB[NN * DD], g_hlB[NN * DD];
__device__ bf16  g_winh[DD * DD], g_winl[DD * DD];
__device__ bf16  g_Mh[NL * DD * DD];                    // wq wk^T (bf16 hi)
__device__ bf16  g_Wh[NL * DD * DD];                    // wv wp   (bf16 hi)
__device__ int   g_deg[NN];
__device__ int   g_off[NN + 1];
__device__ int   g_cur[NN];
__device__ int   g_bt[40];
__device__ int   g_srcs[NE];

// ---------------- helpers -----------------------------------------------------
__device__ __forceinline__ void f32split(float v, bf16& h, bf16& l) {
    h = __float2bfloat16(v);
    l = __float2bfloat16(v - __bfloat162float(h));
}
__device__ __forceinline__ void ldsm4(uint& r0, uint& r1, uint& r2, uint& r3, uint addr) {
    asm volatile("ldmatrix.sync.aligned.m8n8.x4.shared.b16 {%0,%1,%2,%3}, [%4];"
                 : "=r"(r0), "=r"(r1), "=r"(r2), "=r"(r3) : "r"(addr));
}
__device__ __forceinline__ void ldsm4t(uint& r0, uint& r1, uint& r2, uint& r3, uint addr) {
    asm volatile("ldmatrix.sync.aligned.m8n8.x4.trans.shared.b16 {%0,%1,%2,%3}, [%4];"
                 : "=r"(r0), "=r"(r1), "=r"(r2), "=r"(r3) : "r"(addr));
}
__device__ __forceinline__ void mma_bf16(float* c, const uint* a, uint b0, uint b1) {
    asm volatile("mma.sync.aligned.m16n8k16.row.col.f32.bf16.bf16.f32 "
                 "{%0,%1,%2,%3},{%4,%5,%6,%7},{%8,%9},{%0,%1,%2,%3};"
                 : "+f"(c[0]), "+f"(c[1]), "+f"(c[2]), "+f"(c[3])
                 : "r"(a[0]), "r"(a[1]), "r"(a[2]), "r"(a[3]), "r"(b0), "r"(b1));
}
__device__ __forceinline__ void cp16(uint dst, const void* src) {
    asm volatile("cp.async.cg.shared.global [%0], [%1], 16;" :: "r"(dst), "l"(src));
}
__device__ __forceinline__ void cp16z(uint dst, const void* src, uint sz) {
    asm volatile("cp.async.cg.shared.global [%0], [%1], 16, %2;" :: "r"(dst), "l"(src), "r"(sz));
}
__device__ __forceinline__ void cp_commit() { asm volatile("cp.async.commit_group;"); }

// ---------------- CSR build ----------------------------------------------------
__global__ void k_init() {
    int i = blockIdx.x * blockDim.x + threadIdx.x;
    if (i < NN) { g_deg[i] = 0; g_cur[i] = 0; }
}
__global__ void k_hist(const int* __restrict__ dst) {
    int e = blockIdx.x * blockDim.x + threadIdx.x;
    if (e < NE) atomicAdd(&g_deg[dst[e]], 1);
}
__global__ __launch_bounds__(256) void k_scan_part() {
    __shared__ int ws[8];
    int b = blockIdx.x, tid = threadIdx.x;
    int lane = tid & 31, wid = tid >> 5;
    int i = b * 256 + tid;
    int x = (i < NN) ? g_deg[i] : 0;
    int v = x;
    #pragma unroll
    for (int o = 1; o < 32; o <<= 1) {
        int y = __shfl_up_sync(0xffffffffu, v, o);
        if (lane >= o) v += y;
    }
    if (lane == 31) ws[wid] = v;
    __syncthreads();
    if (tid < 8) {
        int w = ws[tid];
        #pragma unroll
        for (int o = 1; o < 8; o <<= 1) {
            int y = __shfl_up_sync(0xffu, w, o);
            if (tid >= o) w += y;
        }
        ws[tid] = w;
    }
    __syncthreads();
    int add = wid ? ws[wid - 1] : 0;
    if (i < NN) g_off[i] = add + v - x;
    if (tid == 255) g_bt[b] = add + v;
}
__global__ void k_scan_top() {
    int tid = threadIdx.x;
    int v = (tid < 40) ? g_bt[tid] : 0;
    int e = v;
    #pragma unroll
    for (int o = 1; o < 64; o <<= 1) {
        int y = __shfl_up_sync(0xffffffffu, e, o);
        if ((threadIdx.x & 31) >= o) e += y;
    }
    __shared__ int carry;
    if (tid == 31) carry = e;
    __syncthreads();
    if (tid < 40) {
        int ex = e - v + ((tid >= 32) ? carry : 0);
        g_bt[tid] = ex;
    }
    if (tid == 0) g_off[NN] = NE;
}
__global__ __launch_bounds__(256) void k_scan_add() {
    int b = blockIdx.x;
    int i = b * 256 + threadIdx.x;
    if (b > 0 && i < NN) g_off[i] += g_bt[b];
}
__global__ void k_scatter(const int* __restrict__ src, const int* __restrict__ dst) {
    int e = blockIdx.x * blockDim.x + threadIdx.x;
    if (e < NE) {
        int d = dst[e];
        int pos = g_off[d] + atomicAdd(&g_cur[d], 1);
        g_srcs[pos] = src[e];
    }
}

// ---------------- fused fp32 -> bf16 hi/lo (x and w_in) -------------------------
__global__ void k_cvt2(const float* __restrict__ a, bf16* __restrict__ ah,
                       bf16* __restrict__ al, int na,
                       const float* __restrict__ b, bf16* __restrict__ bh,
                       bf16* __restrict__ bl, int nb) {
    int i = blockIdx.x * blockDim.x + threadIdx.x;
    if (i < na) {
        bf16 h, l; f32split(a[i], h, l); ah[i] = h; al[i] = l;
    } else if (i < na + nb) {
        int j = i - na;
        bf16 h, l; f32split(b[j], h, l); bh[j] = h; bl[j] = l;
    }
}

// ---------------- weight folding (bf16-hi outputs) -------------------------------
__global__ __launch_bounds__(256) void k_small(
    const float* __restrict__ wq, const float* __restrict__ wk,
    const float* __restrict__ wv, const float* __restrict__ wp,
    bf16* __restrict__ pMh, bf16* __restrict__ pWh)
{
    int z = blockIdx.z;
    const float* A; const float* B; bf16* Ch; int tb;
    if (z < 3) { A = wq + z * DD * DD; B = wk + z * DD * DD;
                 Ch = pMh + z * DD * DD; tb = 1; }
    else       { A = wv + (z - 3) * DD * DD; B = wp + (z - 3) * DD * DD;
                 Ch = pWh + (z - 3) * DD * DD; tb = 0; }

    __shared__ float As[16][65];
    __shared__ float Bs[16][65];
    int tid = threadIdx.x;
    int tx = tid & 15, ty = tid >> 4;
    int row0 = blockIdx.y * 64, col0 = blockIdx.x * 64;
    float acc[4][4] = {};

    for (int kt = 0; kt < DD; kt += 16) {
        {
            int r = tid >> 2, c = (tid & 3) * 4;
            float4 v = *(const float4*)(A + (row0 + r) * DD + kt + c);
            As[c + 0][r] = v.x; As[c + 1][r] = v.y; As[c + 2][r] = v.z; As[c + 3][r] = v.w;
        }
        if (tb) {
            int c = tid >> 2, k = (tid & 3) * 4;
            float4 v = *(const float4*)(B + (col0 + c) * DD + kt + k);
            Bs[k + 0][c] = v.x; Bs[k + 1][c] = v.y; Bs[k + 2][c] = v.z; Bs[k + 3][c] = v.w;
        } else {
            int k = tid >> 4, c = (tid & 15) * 4;
            float4 v = *(const float4*)(B + (kt + k) * DD + col0 + c);
            Bs[k][c + 0] = v.x; Bs[k][c + 1] = v.y; Bs[k][c + 2] = v.z; Bs[k][c + 3] = v.w;
        }
        __syncthreads();
        #pragma unroll
        for (int kk = 0; kk < 16; kk++) {
            float a[4], b[4];
            #pragma unroll
            for (int i = 0; i < 4; i++) { a[i] = As[kk][ty * 4 + i]; b[i] = Bs[kk][tx * 4 + i]; }
            #pragma unroll
            for (int i = 0; i < 4; i++)
                #pragma unroll
                for (int j = 0; j < 4; j++)
                    acc[i][j] += a[i] * b[j];
        }
        __syncthreads();
    }
    #pragma unroll
    for (int i = 0; i < 4; i++)
        #pragma unroll
        for (int j = 0; j < 4; j++)
            Ch[(row0 + ty * 4 + i) * DD + col0 + tx * 4 + j] = __float2bfloat16(acc[i][j]);
}

// ---------------- h0 GEMM: 64x128 tile, 3 products, occ 2 -----------------------
#define STH_ELEMS 13824
#define A_PITCH 40
#define B_PITCH 136

__global__ __launch_bounds__(256, 2) void k_mma_h0(
    const bf16* __restrict__ Ah, const bf16* __restrict__ Al,
    const bf16* __restrict__ Bh, const bf16* __restrict__ Bl,
    const float* __restrict__ bias,
    bf16* __restrict__ Chi, bf16* __restrict__ Clo)
{
    extern __shared__ __align__(16) bf16 smem[];
    int tid = threadIdx.x;
    int lane = tid & 31, warp = tid >> 5;
    int wm = warp & 1, wn = warp >> 1;
    int row0 = blockIdx.y * 64, col0 = blockIdx.x * 128;

    uint sbase = (uint)__cvta_generic_to_shared(smem);
    int a_r0 = tid >> 2,        a_c0 = (tid & 3) * 8;
    int b_r0 = tid >> 4,        b_c0 = (tid & 15) * 8;
    int b_r1 = (tid + 256) >> 4;

    int ga0 = row0 + a_r0;
    uint sz0 = (ga0 < NN) ? 16u : 0u;
    int ca0 = (ga0 < NN) ? ga0 : 0;

    auto issue = [&](int st, int kt) {
        uint base = sbase + (uint)(st * STH_ELEMS) * 2u;
        uint dA0 = base + (uint)(a_r0 * A_PITCH + a_c0) * 2u;
        cp16z(dA0,            Ah + (size_t)ca0 * DD + kt + a_c0, sz0);
        cp16z(dA0 + 2560u*2u, Al + (size_t)ca0 * DD + kt + a_c0, sz0);
        uint dB0 = base + (5120u + (uint)(b_r0 * B_PITCH + b_c0)) * 2u;
        uint dB1 = base + (5120u + (uint)(b_r1 * B_PITCH + b_c0)) * 2u;
        cp16(dB0, Bh + (size_t)(kt + b_r0) * DD + col0 + b_c0);
        cp16(dB1, Bh + (size_t)(kt + b_r1) * DD + col0 + b_c0);
        cp16(dB0 + 4352u*2u, Bl + (size_t)(kt + b_r0) * DD + col0 + b_c0);
        cp16(dB1 + 4352u*2u, Bl + (size_t)(kt + b_r1) * DD + col0 + b_c0);
    };

    float acc[2][4][4] = {};
    issue(0, 0);   cp_commit();
    issue(1, 32);  cp_commit();

    #pragma unroll
    for (int i = 0; i < 8; i++) {
        if (i < 7) asm volatile("cp.async.wait_group 1;");
        else       asm volatile("cp.async.wait_group 0;");
        __syncthreads();
        if (i < 6) { issue((i + 2) % 3, (i + 2) * 32); cp_commit(); }

        int st = i % 3;
        uint base = sbase + (uint)(st * STH_ELEMS) * 2u;
        uint aAh = base, aAl = base + 2560u * 2u;
        uint aBh = base + 5120u * 2u, aBl = base + 9472u * 2u;

        #pragma unroll
        for (int ks = 0; ks < 32; ks += 16) {
            int arow = lane & 15;
            int kcol = ks + ((lane >> 4) << 3);
            uint ah[2][4], al[2][4];
            #pragma unroll
            for (int mi = 0; mi < 2; mi++) {
                uint off = (uint)((wm * 32 + mi * 16 + arow) * A_PITCH + kcol) * 2u;
                ldsm4(ah[mi][0], ah[mi][1], ah[mi][2], ah[mi][3], aAh + off);
                ldsm4(al[mi][0], al[mi][1], al[mi][2], al[mi][3], aAl + off);
            }
            uint bhf[2][4], blf[2][4];
            int brow = ks + (lane & 15);
            #pragma unroll
            for (int ng = 0; ng < 2; ng++) {
                int bcol = wn * 32 + ng * 16 + ((lane >> 4) << 3);
                uint off = (uint)(brow * B_PITCH + bcol) * 2u;
                ldsm4t(bhf[ng][0], bhf[ng][1], bhf[ng][2], bhf[ng][3], aBh + off);
                ldsm4t(blf[ng][0], blf[ng][1], blf[ng][2], blf[ng][3], aBl + off);
            }
            #pragma unroll
            for (int mi = 0; mi < 2; mi++)
                #pragma unroll
                for (int ng = 0; ng < 2; ng++) {
                    mma_bf16(acc[mi][ng * 2],     ah[mi], bhf[ng][0], bhf[ng][1]);
                    mma_bf16(acc[mi][ng * 2 + 1], ah[mi], bhf[ng][2], bhf[ng][3]);
                }
            #pragma unroll
            for (int mi = 0; mi < 2; mi++)
                #pragma unroll
                for (int ng = 0; ng < 2; ng++) {
                    mma_bf16(acc[mi][ng * 2],     al[mi], bhf[ng][0], bhf[ng][1]);
                    mma_bf16(acc[mi][ng * 2 + 1], al[mi], bhf[ng][2], bhf[ng][3]);
                }
            #pragma unroll
            for (int mi = 0; mi < 2; mi++)
                #pragma unroll
                for (int ng = 0; ng < 2; ng++) {
                    mma_bf16(acc[mi][ng * 2],     ah[mi], blf[ng][0], blf[ng][1]);
                    mma_bf16(acc[mi][ng * 2 + 1], ah[mi], blf[ng][2], blf[ng][3]);
                }
        }
    }

    int grp = lane >> 2, q = lane & 3;
    #pragma unroll
    for (int mi = 0; mi < 2; mi++) {
        int rb = row0 + wm * 32 + mi * 16 + grp;
        #pragma unroll
        for (int nj = 0; nj < 4; nj++) {
            int cb = col0 + wn * 32 + nj * 8 + q * 2;
            float b0 = bias[cb], b1 = bias[cb + 1];
            float v0 = fmaxf(acc[mi][nj][0] + b0, 0.f);
            float v1 = fmaxf(acc[mi][nj][1] + b1, 0.f);
            float v2 = fmaxf(acc[mi][nj][2] + b0, 0.f);
            float v3 = fmaxf(acc[mi][nj][3] + b1, 0.f);
            if (rb < NN) {
                size_t o = (size_t)rb * DD + cb;
                bf16 h0, l0, h1, l1;
                f32split(v0, h0, l0); f32split(v1, h1, l1);
                Chi[o] = h0; Chi[o + 1] = h1;
                Clo[o] = l0; Clo[o + 1] = l1;
            }
            if (rb + 8 < NN) {
                size_t o = (size_t)(rb + 8) * DD + cb;
                bf16 h2, l2, h3, l3;
                f32split(v2, h2, l2); f32split(v3, h3, l3);
                Chi[o] = h2; Chi[o + 1] = h3;
                Clo[o] = l2; Clo[o + 1] = l3;
            }
        }
    }
}

// ---------------- fused t-GEMM + edge aggregation --------------------------------
// Phase A: t_tile[64][256] = (Ah+Al)[64 rows] @ Mh (t stays in smem).
// Phase B: acc -> smem t-buffer.  Phase C: per-node online-softmax over edges.
#define STE_ELEMS 13568          // Ah 2560 + Al 2560 + B 32x264=8448
#define TB_PITCH 264
#define TS_PITCH 260

__global__ __launch_bounds__(512, 1) void k_tedge(
    const bf16* __restrict__ Ah, const bf16* __restrict__ Al,
    const bf16* __restrict__ Mh,
    bf16* __restrict__ agg_hi, bf16* __restrict__ agg_lo)
{
    extern __shared__ __align__(16) bf16 smem[];
    int tid = threadIdx.x;
    int lane = tid & 31, warp = tid >> 5;   // 16 warps
    int wm = warp & 1, wn = warp >> 1;      // 2 M-warps x 8 N-warps (32x32 tiles)
    int row0 = blockIdx.x * 64;

    uint sbase = (uint)__cvta_generic_to_shared(smem);

    // A: 512 chunks (256 hi + 256 lo); one per thread
    int abuf = tid >> 8;
    int ac = tid & 255;
    int a_r = ac >> 2, a_c = (ac & 3) * 8;
    int ga = row0 + a_r;
    uint sza = (ga < NN) ? 16u : 0u;
    int ca = (ga < NN) ? ga : 0;
    const bf16* Asrc = abuf ? Al : Ah;
    uint aoff = (uint)(abuf * 2560 + a_r * A_PITCH + a_c) * 2u;

    // B: 1024 chunks; two per thread
    int b_r0 = tid >> 5,          b_p0 = (tid & 31) * 8;
    int b_r1 = (tid + 512) >> 5,  b_p1 = (tid & 31) * 8;

    auto issue = [&](int st, int kt) {
        uint base = sbase + (uint)(st * STE_ELEMS) * 2u;
        cp16z(base + aoff, Asrc + (size_t)ca * DD + kt + a_c, sza);
        cp16(base + (5120u + (uint)(b_r0 * TB_PITCH + b_p0)) * 2u,
             Mh + (size_t)(kt + b_r0) * DD + b_p0);
        cp16(base + (5120u + (uint)(b_r1 * TB_PITCH + b_p1)) * 2u,
             Mh + (size_t)(kt + b_r1) * DD + b_p1);
    };

    float acc[2][4][4] = {};
    issue(0, 0);   cp_commit();
    issue(1, 32);  cp_commit();

    #pragma unroll
    for (int i = 0; i < 8; i++) {
        if (i < 7) asm volatile("cp.async.wait_group 1;");
        else       asm volatile("cp.async.wait_group 0;");
        __syncthreads();
        if (i < 6) { issue((i + 2) % 3, (i + 2) * 32); cp_commit(); }

        int st = i % 3;
        uint base = sbase + (uint)(st * STE_ELEMS) * 2u;
        uint aAh = base, aAl = base + 2560u * 2u;
        uint aB  = base + 5120u * 2u;

        #pragma unroll
        for (int ks = 0; ks < 32; ks += 16) {
            int arow = lane & 15;
            int kcol = ks + ((lane >> 4) << 3);
            uint ah[2][4], al[2][4];
            #pragma unroll
            for (int mi = 0; mi < 2; mi++) {
                uint off = (uint)((wm * 32 + mi * 16 + arow) * A_PITCH + kcol) * 2u;
                ldsm4(ah[mi][0], ah[mi][1], ah[mi][2], ah[mi][3], aAh + off);
                ldsm4(al[mi][0], al[mi][1], al[mi][2], al[mi][3], aAl + off);
            }
            uint bhf[2][4];
            int brow = ks + (lane & 15);
            #pragma unroll
            for (int ng = 0; ng < 2; ng++) {
                int bcol = wn * 32 + ng * 16 + ((lane >> 4) << 3);
                uint off = (uint)(brow * TB_PITCH + bcol) * 2u;
                ldsm4t(bhf[ng][0], bhf[ng][1], bhf[ng][2], bhf[ng][3], aB + off);
            }
            #pragma unroll
            for (int mi = 0; mi < 2; mi++)
                #pragma unroll
                for (int ng = 0; ng < 2; ng++) {
                    mma_bf16(acc[mi][ng * 2],     ah[mi], bhf[ng][0], bhf[ng][1]);
                    mma_bf16(acc[mi][ng * 2 + 1], ah[mi], bhf[ng][2], bhf[ng][3]);
                }
            #pragma unroll
            for (int mi = 0; mi < 2; mi++)
                #pragma unroll
                for (int ng = 0; ng < 2; ng++) {
                    mma_bf16(acc[mi][ng * 2],     al[mi], bhf[ng][0], bhf[ng][1]);
                    mma_bf16(acc[mi][ng * 2 + 1], al[mi], bhf[ng][2], bhf[ng][3]);
                }
        }
    }

    // ---- Phase B: write t tile (64 x 256 fp32) into smem
    __syncthreads();
    float* ts = (float*)smem;
    int grp = lane >> 2, q = lane & 3;
    #pragma unroll
    for (int mi = 0; mi < 2; mi++) {
        int r = wm * 32 + mi * 16 + grp;
        #pragma unroll
        for (int nj = 0; nj < 4; nj++) {
            int cc = wn * 32 + nj * 8 + q * 2;
            ts[r * TS_PITCH + cc]     = acc[mi][nj][0];
            ts[r * TS_PITCH + cc + 1] = acc[mi][nj][1];
            ts[(r + 8) * TS_PITCH + cc]     = acc[mi][nj][2];
            ts[(r + 8) * TS_PITCH + cc + 1] = acc[mi][nj][3];
        }
    }
    __syncthreads();

    // ---- Phase C: per-node online-softmax aggregation (warp = 4 nodes)
    int c0 = lane * 8;
    for (int iv = 0; iv < 4; iv++) {
        int ln = warp * 4 + iv;
        int n = row0 + ln;
        if (n >= NN) continue;

        float t8[8];
        *(float4*)&t8[0] = *(const float4*)(ts + ln * TS_PITCH + c0);
        *(float4*)&t8[4] = *(const float4*)(ts + ln * TS_PITCH + c0 + 4);

        float m = -INFINITY, s = 0.f;
        float aacc[8] = {};

        int e0 = g_off[n], e1 = g_off[n + 1];
        uint4 hv0, hv1;
        if (e0 < e1) {
            int sN = g_srcs[e0];
            hv0 = *(const uint4*)(Ah + (size_t)sN * DD + c0);
        }
        if (e0 + 1 < e1) {
            int sN = g_srcs[e0 + 1];
            hv1 = *(const uint4*)(Ah + (size_t)sN * DD + c0);
        }
        for (int e = e0; e < e1; e++) {
            uint4 hv = hv0;
            hv0 = hv1;
            if (e + 2 < e1) {
                int sN = g_srcs[e + 2];
                hv1 = *(const uint4*)(Ah + (size_t)sN * DD + c0);
            }

            const __nv_bfloat162* hp = (const __nv_bfloat162*)&hv;
            float hf[8];
            #pragma unroll
            for (int j = 0; j < 4; j++) {
                float2 f = __bfloat1622float2(hp[j]);
                hf[2 * j] = f.x; hf[2 * j + 1] = f.y;
            }
            float d = 0.f;
            #pragma unroll
            for (int j = 0; j < 8; j++) d += t8[j] * hf[j];
            #pragma unroll
            for (int o = 16; o > 0; o >>= 1) d += __shfl_xor_sync(0xffffffffu, d, o);
            d *= 0.0625f;

            float nm = fmaxf(m, d);
            float c = __expf(m - nm);
            float w = __expf(d - nm);
            s = s * c + w;
            m = nm;

            #pragma unroll
            for (int j = 0; j < 8; j++)
                aacc[j] = aacc[j] * c + w * hf[j];
        }

        float inv = 1.0f / (s + 1e-9f);
        bf16 hh8[8], hl8[8];
        #pragma unroll
        for (int j = 0; j < 8; j++) f32split(aacc[j] * inv, hh8[j], hl8[j]);
        *(uint4*)(agg_hi + (size_t)n * DD + c0) = *(uint4*)&hh8[0];
        *(uint4*)(agg_lo + (size_t)n * DD + c0) = *(uint4*)&hl8[0];
    }
}

// ---------------- p-GEMM (2 products, residual epilogue), 64x128, occ 3 ---------
#define STG_ELEMS 9472

__global__ __launch_bounds__(256, 3) void k_gemm(
    const bf16* __restrict__ Ah, const bf16* __restrict__ Al,
    const bf16* __restrict__ Bh,
    float* __restrict__ f32_out, const float* __restrict__ bias,
    const bf16* __restrict__ rhh, const bf16* __restrict__ rhl,
    bf16* __restrict__ Chi, bf16* __restrict__ Clo)
{
    extern __shared__ __align__(16) bf16 smem[];
    int col0 = blockIdx.x * 128;
    int row0 = blockIdx.y * 64;

    int tid = threadIdx.x;
    int lane = tid & 31, warp = tid >> 5;
    int wm = warp & 1, wn = warp >> 1;

    uint sbase = (uint)__cvta_generic_to_shared(smem);
    int a_r0 = tid >> 2,        a_c0 = (tid & 3) * 8;
    int b_r0 = tid >> 4,        b_c0 = (tid & 15) * 8;
    int b_r1 = (tid + 256) >> 4;

    int ga0 = row0 + a_r0;
    uint sz0 = (ga0 < NN) ? 16u : 0u;
    int ca0 = (ga0 < NN) ? ga0 : 0;

    auto issue = [&](int st, int kt) {
        uint base = sbase + (uint)(st * STG_ELEMS) * 2u;
        uint dA0 = base + (uint)(a_r0 * A_PITCH + a_c0) * 2u;
        cp16z(dA0,            Ah + (size_t)ca0 * DD + kt + a_c0, sz0);
        cp16z(dA0 + 2560u*2u, Al + (size_t)ca0 * DD + kt + a_c0, sz0);
        uint dB0 = base + (5120u + (uint)(b_r0 * B_PITCH + b_c0)) * 2u;
        uint dB1 = base + (5120u + (uint)(b_r1 * B_PITCH + b_c0)) * 2u;
        cp16(dB0, Bh + (size_t)(kt + b_r0) * DD + col0 + b_c0);
        cp16(dB1, Bh + (size_t)(kt + b_r1) * DD + col0 + b_c0);
    };

    float acc[2][4][4] = {};
    issue(0, 0);   cp_commit();
    issue(1, 32);  cp_commit();

    #pragma unroll
    for (int i = 0; i < 8; i++) {
        if (i < 7) asm volatile("cp.async.wait_group 1;");
        else       asm volatile("cp.async.wait_group 0;");
        __syncthreads();
        if (i < 6) { issue((i + 2) % 3, (i + 2) * 32); cp_commit(); }

        int st = i % 3;
        uint base = sbase + (uint)(st * STG_ELEMS) * 2u;
        uint aAh = base, aAl = base + 2560u * 2u;
        uint aBh = base + 5120u * 2u;

        #pragma unroll
        for (int ks = 0; ks < 32; ks += 16) {
            int arow = lane & 15;
            int kcol = ks + ((lane >> 4) << 3);
            uint ah[2][4], al[2][4];
            #pragma unroll
            for (int mi = 0; mi < 2; mi++) {
                uint off = (uint)((wm * 32 + mi * 16 + arow) * A_PITCH + kcol) * 2u;
                ldsm4(ah[mi][0], ah[mi][1], ah[mi][2], ah[mi][3], aAh + off);
                ldsm4(al[mi][0], al[mi][1], al[mi][2], al[mi][3], aAl + off);
            }
            uint bhf[2][4];
            int brow = ks + (lane & 15);
            #pragma unroll
            for (int ng = 0; ng < 2; ng++) {
                int bcol = wn * 32 + ng * 16 + ((lane >> 4) << 3);
                uint off = (uint)(brow * B_PITCH + bcol) * 2u;
                ldsm4t(bhf[ng][0], bhf[ng][1], bhf[ng][2], bhf[ng][3], aBh + off);
            }
            #pragma unroll
            for (int mi = 0; mi < 2; mi++)
                #pragma unroll
                for (int ng = 0; ng < 2; ng++) {
                    mma_bf16(acc[mi][ng * 2],     ah[mi], bhf[ng][0], bhf[ng][1]);
                    mma_bf16(acc[mi][ng * 2 + 1], ah[mi], bhf[ng][2], bhf[ng][3]);
                }
            #pragma unroll
            for (int mi = 0; mi < 2; mi++)
                #pragma unroll
                for (int ng = 0; ng < 2; ng++) {
                    mma_bf16(acc[mi][ng * 2],     al[mi], bhf[ng][0], bhf[ng][1]);
                    mma_bf16(acc[mi][ng * 2 + 1], al[mi], bhf[ng][2], bhf[ng][3]);
                }
        }
    }

    int grp = lane >> 2, q = lane & 3;
    #pragma unroll
    for (int mi = 0; mi < 2; mi++) {
        int rb = row0 + wm * 32 + mi * 16 + grp;
        #pragma unroll
        for (int nj = 0; nj < 4; nj++) {
            int cb = col0 + wn * 32 + nj * 8 + q * 2;
            float v0 = acc[mi][nj][0], v1 = acc[mi][nj][1];
            float v2 = acc[mi][nj][2], v3 = acc[mi][nj][3];
            {
                float b0 = bias[cb], b1 = bias[cb + 1];
                size_t o0 = (size_t)rb * DD + cb;
                size_t o1 = (size_t)(rb + 8) * DD + cb;
                float r00 = 0.f, r01 = 0.f, r10 = 0.f, r11 = 0.f;
                if (rb < NN) {
                    float2 a2 = __bfloat1622float2(*(const __nv_bfloat162*)(rhh + o0));
                    float2 b2 = __bfloat1622float2(*(const __nv_bfloat162*)(rhl + o0));
                    r00 = a2.x + b2.x; r01 = a2.y + b2.y;
                }
                if (rb + 8 < NN) {
                    float2 a2 = __bfloat1622float2(*(const __nv_bfloat162*)(rhh + o1));
                    float2 b2 = __bfloat1622float2(*(const __nv_bfloat162*)(rhl + o1));
                    r10 = a2.x + b2.x; r11 = a2.y + b2.y;
                }
                v0 = fmaxf(v0 + b0 + r00, 0.f);
                v1 = fmaxf(v1 + b1 + r01, 0.f);
                v2 = fmaxf(v2 + b0 + r10, 0.f);
                v3 = fmaxf(v3 + b1 + r11, 0.f);
            }
            if (rb < NN) {
                size_t o = (size_t)rb * DD + cb;
                if (f32_out) { f32_out[o] = v0; f32_out[o + 1] = v1; }
                if (Chi) {
                    bf16 h0, l0, h1, l1;
                    f32split(v0, h0, l0); f32split(v1, h1, l1);
                    Chi[o] = h0; Chi[o + 1] = h1;
                    Clo[o] = l0; Clo[o + 1] = l1;
                }
            }
            if (rb + 8 < NN) {
                size_t o = (size_t)(rb + 8) * DD + cb;
                if (f32_out) { f32_out[o] = v2; f32_out[o + 1] = v3; }
                if (Chi) {
                    bf16 h2, l2, h3, l3;
                    f32split(v2, h2, l2); f32split(v3, h3, l3);
                    Chi[o] = h2; Chi[o + 1] = h3;
                    Clo[o] = l2; Clo[o + 1] = l3;
                }
            }
        }
    }
}

// ---------------- launch ----------------------------------------------------------
extern "C" void kernel_launch(void* const* d_in, const int* in_sizes, int n_in,
                              void* d_out, int out_size)
{
    const float* x    = (const float*)d_in[0];
    const int*   edges= (const int*)  d_in[1];
    const float* w_in = (const float*)d_in[2];
    const float* b_in = (const float*)d_in[3];
    const float* wq   = (const float*)d_in[4];
    const float* wk   = (const float*)d_in[5];
    const float* wv   = (const float*)d_in[6];
    const float* wp   = (const float*)d_in[7];
    const float* bp   = (const float*)d_in[8];
    float* out = (float*)d_out;

    const int* src = edges;
    const int* dst = edges + NE;

    bf16 *pxh, *pxl, *phhA, *phlA, *phhB, *phlB, *pwinh, *pwinl, *pMh, *pWh;
    cudaGetSymbolAddress((void**)&pxh,   g_xh);
    cudaGetSymbolAddress((void**)&pxl,   g_xl);
    cudaGetSymbolAddress((void**)&phhA,  g_hhA);
    cudaGetSymbolAddress((void**)&phlA,  g_hlA);
    cudaGetSymbolAddress((void**)&phhB,  g_hhB);
    cudaGetSymbolAddress((void**)&phlB,  g_hlB);
    cudaGetSymbolAddress((void**)&pwinh, g_winh);
    cudaGetSymbolAddress((void**)&pwinl, g_winl);
    cudaGetSymbolAddress((void**)&pMh,   g_Mh);
    cudaGetSymbolAddress((void**)&pWh,   g_Wh);

    static cudaStream_t s_side = nullptr;
    static cudaEvent_t s_ev0 = nullptr, s_ev1 = nullptr;
    if (!s_side) {
        cudaFuncSetAttribute(k_mma_h0, cudaFuncAttributeMaxDynamicSharedMemorySize,
                             3 * STH_ELEMS * 2);
        cudaFuncSetAttribute(k_gemm, cudaFuncAttributeMaxDynamicSharedMemorySize,
                             3 * STG_ELEMS * 2);
        cudaFuncSetAttribute(k_tedge, cudaFuncAttributeMaxDynamicSharedMemorySize,
                             3 * STE_ELEMS * 2);
        cudaStreamCreateWithFlags(&s_side, cudaStreamNonBlocking);
        cudaEventCreateWithFlags(&s_ev0, cudaEventDisableTiming);
        cudaEventCreateWithFlags(&s_ev1, cudaEventDisableTiming);
    }

    dim3 gw(2, 157);   // 64-row tiles

    // ---- fork: weight folding + CSR on side stream (slot 6 = k_mma_h0)
    cudaEventRecord(s_ev0, 0);
    cudaStreamWaitEvent(s_side, s_ev0, 0);
    k_small    <<<dim3(4, 4, 6), 256, 0, s_side>>>(wq, wk, wv, wp, pMh, pWh);   // 1
    k_init     <<<(NN + 255) / 256, 256, 0, s_side>>>();                        // 2
    k_hist     <<<(NE + 255) / 256, 256, 0, s_side>>>(dst);                     // 3
    k_scan_part<<<40, 256, 0, s_side>>>();                                      // 4
    // ---- main: conversions + h0
    k_cvt2<<<(NN * DD + DD * DD + 255) / 256, 256>>>(                           // 5
        x, pxh, pxl, NN * DD, w_in, pwinh, pwinl, DD * DD);
    k_mma_h0<<<gw, 256, 3 * STH_ELEMS * 2>>>(                                   // 6 (profiled)
        pxh, pxl, pwinh, pwinl, b_in, phhA, phlA);
    // ---- side: finish CSR
    k_scan_top <<<1, 64, 0, s_side>>>();
    k_scan_add <<<40, 256, 0, s_side>>>();
    k_scatter  <<<(NE + 255) / 256, 256, 0, s_side>>>(src, dst);
    cudaEventRecord(s_ev1, s_side);

    // join: tedge needs pMh + CSR
    cudaStreamWaitEvent(0, s_ev1, 0);

    bf16* paggh = pxh;   // agg buffers reuse x hi/lo
    bf16* paggl = pxl;

    bf16* chh = phhA; bf16* chl = phlA;
    bf16* nhh = phhB; bf16* nhl = phlB;
    for (int l = 0; l < NL; l++) {
        // fused t-GEMM + edge aggregation
        k_tedge<<<157, 512, 3 * STE_ELEMS * 2>>>(
            chh, chl, pMh + l * DD * DD, paggh, paggl);
        // p GEMM: hnext = relu(agg @ wvp + bp + h)
        float* ho = (l == NL - 1) ? out : nullptr;
        bf16* oh = (l == NL - 1) ? nullptr : nhh;
        bf16* ol = (l == NL - 1) ? nullptr : nhl;
        k_gemm<<<gw, 256, 3 * STG_ELEMS * 2>>>(
            paggh, paggl, pWh + l * DD * DD, ho,
            bp + l * DD, chh, chl, oh, ol);
        bf16* t1 = chh; chh = nhh; nhh = t1;
        bf16* t2 = chl; chl = nhl; nhl = t2;
    }
}

// round 13
// speedup vs baseline: 1.3981x; 1.3981x over previous
#include <cuda_runtime.h>
#include <cuda_bf16.h>
#include <stdint.h>
#include <math.h>

#define NN 10000
#define NE 320000
#define DD 256
#define NL 3

typedef __nv_bfloat16 bf16;
typedef unsigned int uint;

// ---------------- scratch -----------------------------------------------------
__device__ float g_t[NN * DD];
__device__ bf16  g_xh[NN * DD], g_xl[NN * DD];          // x hi/lo, reused as agg hi/lo
__device__ bf16  g_hhA[NN * DD], g_hlA[NN * DD];
__device__ bf16  g_hhB[NN * DD], g_hlB[NN * DD];
__device__ bf16  g_winh[DD * DD], g_winl[DD * DD];
__device__ bf16  g_Mh[NL * DD * DD];                    // wq wk^T (bf16 hi)
__device__ bf16  g_Wh[NL * DD * DD];                    // wv wp   (bf16 hi)
__device__ int   g_deg[NN];
__device__ int   g_off[NN + 1];
__device__ int   g_cur[NN];
__device__ int   g_bt[40];
__device__ int   g_srcs[NE];

// ---------------- helpers -----------------------------------------------------
__device__ __forceinline__ void f32split(float v, bf16& h, bf16& l) {
    h = __float2bfloat16(v);
    l = __float2bfloat16(v - __bfloat162float(h));
}
__device__ __forceinline__ void ldsm4(uint& r0, uint& r1, uint& r2, uint& r3, uint addr) {
    asm volatile("ldmatrix.sync.aligned.m8n8.x4.shared.b16 {%0,%1,%2,%3}, [%4];"
                 : "=r"(r0), "=r"(r1), "=r"(r2), "=r"(r3) : "r"(addr));
}
__device__ __forceinline__ void ldsm4t(uint& r0, uint& r1, uint& r2, uint& r3, uint addr) {
    asm volatile("ldmatrix.sync.aligned.m8n8.x4.trans.shared.b16 {%0,%1,%2,%3}, [%4];"
                 : "=r"(r0), "=r"(r1), "=r"(r2), "=r"(r3) : "r"(addr));
}
__device__ __forceinline__ void mma_bf16(float* c, const uint* a, uint b0, uint b1) {
    asm volatile("mma.sync.aligned.m16n8k16.row.col.f32.bf16.bf16.f32 "
                 "{%0,%1,%2,%3},{%4,%5,%6,%7},{%8,%9},{%0,%1,%2,%3};"
                 : "+f"(c[0]), "+f"(c[1]), "+f"(c[2]), "+f"(c[3])
                 : "r"(a[0]), "r"(a[1]), "r"(a[2]), "r"(a[3]), "r"(b0), "r"(b1));
}
__device__ __forceinline__ void cp16(uint dst, const void* src) {
    asm volatile("cp.async.cg.shared.global [%0], [%1], 16;" :: "r"(dst), "l"(src));
}
__device__ __forceinline__ void cp16z(uint dst, const void* src, uint sz) {
    asm volatile("cp.async.cg.shared.global [%0], [%1], 16, %2;" :: "r"(dst), "l"(src), "r"(sz));
}
__device__ __forceinline__ void cp_commit() { asm volatile("cp.async.commit_group;"); }

// ---------------- CSR build ----------------------------------------------------
__global__ void k_init() {
    int i = blockIdx.x * blockDim.x + threadIdx.x;
    if (i < NN) { g_deg[i] = 0; g_cur[i] = 0; }
}
__global__ void k_hist(const int* __restrict__ dst) {
    int e = blockIdx.x * blockDim.x + threadIdx.x;
    if (e < NE) atomicAdd(&g_deg[dst[e]], 1);
}
__global__ __launch_bounds__(256) void k_scan_part() {
    __shared__ int ws[8];
    int b = blockIdx.x, tid = threadIdx.x;
    int lane = tid & 31, wid = tid >> 5;
    int i = b * 256 + tid;
    int x = (i < NN) ? g_deg[i] : 0;
    int v = x;
    #pragma unroll
    for (int o = 1; o < 32; o <<= 1) {
        int y = __shfl_up_sync(0xffffffffu, v, o);
        if (lane >= o) v += y;
    }
    if (lane == 31) ws[wid] = v;
    __syncthreads();
    if (tid < 8) {
        int w = ws[tid];
        #pragma unroll
        for (int o = 1; o < 8; o <<= 1) {
            int y = __shfl_up_sync(0xffu, w, o);
            if (tid >= o) w += y;
        }
        ws[tid] = w;
    }
    __syncthreads();
    int add = wid ? ws[wid - 1] : 0;
    if (i < NN) g_off[i] = add + v - x;
    if (tid == 255) g_bt[b] = add + v;
}
__global__ void k_scan_top() {
    int tid = threadIdx.x;
    int v = (tid < 40) ? g_bt[tid] : 0;
    int e = v;
    #pragma unroll
    for (int o = 1; o < 64; o <<= 1) {
        int y = __shfl_up_sync(0xffffffffu, e, o);
        if ((threadIdx.x & 31) >= o) e += y;
    }
    __shared__ int carry;
    if (tid == 31) carry = e;
    __syncthreads();
    if (tid < 40) {
        int ex = e - v + ((tid >= 32) ? carry : 0);
        g_bt[tid] = ex;
    }
    if (tid == 0) g_off[NN] = NE;
}
__global__ __launch_bounds__(256) void k_scan_add() {
    int b = blockIdx.x;
    int i = b * 256 + threadIdx.x;
    if (b > 0 && i < NN) g_off[i] += g_bt[b];
}
__global__ void k_scatter(const int* __restrict__ src, const int* __restrict__ dst) {
    int e = blockIdx.x * blockDim.x + threadIdx.x;
    if (e < NE) {
        int d = dst[e];
        int pos = g_off[d] + atomicAdd(&g_cur[d], 1);
        g_srcs[pos] = src[e];
    }
}

// ---------------- fused fp32 -> bf16 hi/lo (x and w_in) -------------------------
__global__ void k_cvt2(const float* __restrict__ a, bf16* __restrict__ ah,
                       bf16* __restrict__ al, int na,
                       const float* __restrict__ b, bf16* __restrict__ bh,
                       bf16* __restrict__ bl, int nb) {
    int i = blockIdx.x * blockDim.x + threadIdx.x;
    if (i < na) {
        bf16 h, l; f32split(a[i], h, l); ah[i] = h; al[i] = l;
    } else if (i < na + nb) {
        int j = i - na;
        bf16 h, l; f32split(b[j], h, l); bh[j] = h; bl[j] = l;
    }
}

// ---------------- weight folding (bf16-hi outputs) -------------------------------
__global__ __launch_bounds__(256) void k_small(
    const float* __restrict__ wq, const float* __restrict__ wk,
    const float* __restrict__ wv, const float* __restrict__ wp,
    bf16* __restrict__ pMh, bf16* __restrict__ pWh)
{
    int z = blockIdx.z;
    const float* A; const float* B; bf16* Ch; int tb;
    if (z < 3) { A = wq + z * DD * DD; B = wk + z * DD * DD;
                 Ch = pMh + z * DD * DD; tb = 1; }
    else       { A = wv + (z - 3) * DD * DD; B = wp + (z - 3) * DD * DD;
                 Ch = pWh + (z - 3) * DD * DD; tb = 0; }

    __shared__ float As[16][65];
    __shared__ float Bs[16][65];
    int tid = threadIdx.x;
    int tx = tid & 15, ty = tid >> 4;
    int row0 = blockIdx.y * 64, col0 = blockIdx.x * 64;
    float acc[4][4] = {};

    for (int kt = 0; kt < DD; kt += 16) {
        {
            int r = tid >> 2, c = (tid & 3) * 4;
            float4 v = *(const float4*)(A + (row0 + r) * DD + kt + c);
            As[c + 0][r] = v.x; As[c + 1][r] = v.y; As[c + 2][r] = v.z; As[c + 3][r] = v.w;
        }
        if (tb) {
            int c = tid >> 2, k = (tid & 3) * 4;
            float4 v = *(const float4*)(B + (col0 + c) * DD + kt + k);
            Bs[k + 0][c] = v.x; Bs[k + 1][c] = v.y; Bs[k + 2][c] = v.z; Bs[k + 3][c] = v.w;
        } else {
            int k = tid >> 4, c = (tid & 15) * 4;
            float4 v = *(const float4*)(B + (kt + k) * DD + col0 + c);
            Bs[k][c + 0] = v.x; Bs[k][c + 1] = v.y; Bs[k][c + 2] = v.z; Bs[k][c + 3] = v.w;
        }
        __syncthreads();
        #pragma unroll
        for (int kk = 0; kk < 16; kk++) {
            float a[4], b[4];
            #pragma unroll
            for (int i = 0; i < 4; i++) { a[i] = As[kk][ty * 4 + i]; b[i] = Bs[kk][tx * 4 + i]; }
            #pragma unroll
            for (int i = 0; i < 4; i++)
                #pragma unroll
                for (int j = 0; j < 4; j++)
                    acc[i][j] += a[i] * b[j];
        }
        __syncthreads();
    }
    #pragma unroll
    for (int i = 0; i < 4; i++)
        #pragma unroll
        for (int j = 0; j < 4; j++)
            Ch[(row0 + ty * 4 + i) * DD + col0 + tx * 4 + j] = __float2bfloat16(acc[i][j]);
}

// ---------------- h0 GEMM: 64x128 tile, 3 products, occ 2 -----------------------
#define STH_ELEMS 13824
#define A_PITCH 40
#define B_PITCH 136

__global__ __launch_bounds__(256, 2) void k_mma_h0(
    const bf16* __restrict__ Ah, const bf16* __restrict__ Al,
    const bf16* __restrict__ Bh, const bf16* __restrict__ Bl,
    const float* __restrict__ bias,
    bf16* __restrict__ Chi, bf16* __restrict__ Clo)
{
    extern __shared__ __align__(16) bf16 smem[];
    int tid = threadIdx.x;
    int lane = tid & 31, warp = tid >> 5;
    int wm = warp & 1, wn = warp >> 1;
    int row0 = blockIdx.y * 64, col0 = blockIdx.x * 128;

    uint sbase = (uint)__cvta_generic_to_shared(smem);
    int a_r0 = tid >> 2,        a_c0 = (tid & 3) * 8;
    int b_r0 = tid >> 4,        b_c0 = (tid & 15) * 8;
    int b_r1 = (tid + 256) >> 4;

    int ga0 = row0 + a_r0;
    uint sz0 = (ga0 < NN) ? 16u : 0u;
    int ca0 = (ga0 < NN) ? ga0 : 0;

    auto issue = [&](int st, int kt) {
        uint base = sbase + (uint)(st * STH_ELEMS) * 2u;
        uint dA0 = base + (uint)(a_r0 * A_PITCH + a_c0) * 2u;
        cp16z(dA0,            Ah + (size_t)ca0 * DD + kt + a_c0, sz0);
        cp16z(dA0 + 2560u*2u, Al + (size_t)ca0 * DD + kt + a_c0, sz0);
        uint dB0 = base + (5120u + (uint)(b_r0 * B_PITCH + b_c0)) * 2u;
        uint dB1 = base + (5120u + (uint)(b_r1 * B_PITCH + b_c0)) * 2u;
        cp16(dB0, Bh + (size_t)(kt + b_r0) * DD + col0 + b_c0);
        cp16(dB1, Bh + (size_t)(kt + b_r1) * DD + col0 + b_c0);
        cp16(dB0 + 4352u*2u, Bl + (size_t)(kt + b_r0) * DD + col0 + b_c0);
        cp16(dB1 + 4352u*2u, Bl + (size_t)(kt + b_r1) * DD + col0 + b_c0);
    };

    float acc[2][4][4] = {};
    issue(0, 0);   cp_commit();
    issue(1, 32);  cp_commit();

    #pragma unroll
    for (int i = 0; i < 8; i++) {
        if (i < 7) asm volatile("cp.async.wait_group 1;");
        else       asm volatile("cp.async.wait_group 0;");
        __syncthreads();
        if (i < 6) { issue((i + 2) % 3, (i + 2) * 32); cp_commit(); }

        int st = i % 3;
        uint base = sbase + (uint)(st * STH_ELEMS) * 2u;
        uint aAh = base, aAl = base + 2560u * 2u;
        uint aBh = base + 5120u * 2u, aBl = base + 9472u * 2u;

        #pragma unroll
        for (int ks = 0; ks < 32; ks += 16) {
            int arow = lane & 15;
            int kcol = ks + ((lane >> 4) << 3);
            uint ah[2][4], al[2][4];
            #pragma unroll
            for (int mi = 0; mi < 2; mi++) {
                uint off = (uint)((wm * 32 + mi * 16 + arow) * A_PITCH + kcol) * 2u;
                ldsm4(ah[mi][0], ah[mi][1], ah[mi][2], ah[mi][3], aAh + off);
                ldsm4(al[mi][0], al[mi][1], al[mi][2], al[mi][3], aAl + off);
            }
            uint bhf[2][4], blf[2][4];
            int brow = ks + (lane & 15);
            #pragma unroll
            for (int ng = 0; ng < 2; ng++) {
                int bcol = wn * 32 + ng * 16 + ((lane >> 4) << 3);
                uint off = (uint)(brow * B_PITCH + bcol) * 2u;
                ldsm4t(bhf[ng][0], bhf[ng][1], bhf[ng][2], bhf[ng][3], aBh + off);
                ldsm4t(blf[ng][0], blf[ng][1], blf[ng][2], blf[ng][3], aBl + off);
            }
            #pragma unroll
            for (int mi = 0; mi < 2; mi++)
                #pragma unroll
                for (int ng = 0; ng < 2; ng++) {
                    mma_bf16(acc[mi][ng * 2],     ah[mi], bhf[ng][0], bhf[ng][1]);
                    mma_bf16(acc[mi][ng * 2 + 1], ah[mi], bhf[ng][2], bhf[ng][3]);
                }
            #pragma unroll
            for (int mi = 0; mi < 2; mi++)
                #pragma unroll
                for (int ng = 0; ng < 2; ng++) {
                    mma_bf16(acc[mi][ng * 2],     al[mi], bhf[ng][0], bhf[ng][1]);
                    mma_bf16(acc[mi][ng * 2 + 1], al[mi], bhf[ng][2], bhf[ng][3]);
                }
            #pragma unroll
            for (int mi = 0; mi < 2; mi++)
                #pragma unroll
                for (int ng = 0; ng < 2; ng++) {
                    mma_bf16(acc[mi][ng * 2],     ah[mi], blf[ng][0], blf[ng][1]);
                    mma_bf16(acc[mi][ng * 2 + 1], ah[mi], blf[ng][2], blf[ng][3]);
                }
        }
    }

    int grp = lane >> 2, q = lane & 3;
    #pragma unroll
    for (int mi = 0; mi < 2; mi++) {
        int rb = row0 + wm * 32 + mi * 16 + grp;
        #pragma unroll
        for (int nj = 0; nj < 4; nj++) {
            int cb = col0 + wn * 32 + nj * 8 + q * 2;
            float b0 = bias[cb], b1 = bias[cb + 1];
            float v0 = fmaxf(acc[mi][nj][0] + b0, 0.f);
            float v1 = fmaxf(acc[mi][nj][1] + b1, 0.f);
            float v2 = fmaxf(acc[mi][nj][2] + b0, 0.f);
            float v3 = fmaxf(acc[mi][nj][3] + b1, 0.f);
            if (rb < NN) {
                size_t o = (size_t)rb * DD + cb;
                bf16 h0, l0, h1, l1;
                f32split(v0, h0, l0); f32split(v1, h1, l1);
                Chi[o] = h0; Chi[o + 1] = h1;
                Clo[o] = l0; Clo[o + 1] = l1;
            }
            if (rb + 8 < NN) {
                size_t o = (size_t)(rb + 8) * DD + cb;
                bf16 h2, l2, h3, l3;
                f32split(v2, h2, l2); f32split(v3, h3, l3);
                Chi[o] = h2; Chi[o + 1] = h3;
                Clo[o] = l2; Clo[o + 1] = l3;
            }
        }
    }
}

// ---------------- unified 2-product GEMM, 64x128 tile, K-step 64, 2 stages ------
// stage elems: Ah@0 (64x72), Al@4608, B@9216 (64x136); total 17920
#define STG_ELEMS 17920
#define A_PITCH64 72

__global__ __launch_bounds__(256, 2) void k_gemm(
    const bf16* __restrict__ Ah, const bf16* __restrict__ Al,
    const bf16* __restrict__ Bh,
    float* __restrict__ f32_out, const float* __restrict__ bias,
    const bf16* __restrict__ rhh, const bf16* __restrict__ rhl,
    bf16* __restrict__ Chi, bf16* __restrict__ Clo)
{
    extern __shared__ __align__(16) bf16 smem[];
    int col0 = blockIdx.x * 128;
    int row0 = blockIdx.y * 64;

    int tid = threadIdx.x;
    int lane = tid & 31, warp = tid >> 5;
    int wm = warp & 1, wn = warp >> 1;

    uint sbase = (uint)__cvta_generic_to_shared(smem);
    // A: 512 chunks per buf (64 rows x 8 chunks); thread -> chunks tid, tid+256
    int a_r0 = tid >> 3,         a_c0 = (tid & 7) * 8;
    int a_r1 = (tid + 256) >> 3;
    // B: 1024 chunks (64 rows x 16); thread -> tid, +256, +512, +768
    int b_r0 = tid >> 4,         b_c0 = (tid & 15) * 8;

    int ga0 = row0 + a_r0, ga1 = row0 + a_r1;
    uint sz0 = (ga0 < NN) ? 16u : 0u;
    uint sz1 = (ga1 < NN) ? 16u : 0u;
    int ca0 = (ga0 < NN) ? ga0 : 0;
    int ca1 = (ga1 < NN) ? ga1 : 0;

    auto issue = [&](int st, int kt) {
        uint base = sbase + (uint)(st * STG_ELEMS) * 2u;
        uint dA0 = base + (uint)(a_r0 * A_PITCH64 + a_c0) * 2u;
        uint dA1 = base + (uint)(a_r1 * A_PITCH64 + a_c0) * 2u;
        cp16z(dA0,            Ah + (size_t)ca0 * DD + kt + a_c0, sz0);
        cp16z(dA1,            Ah + (size_t)ca1 * DD + kt + a_c0, sz1);
        cp16z(dA0 + 4608u*2u, Al + (size_t)ca0 * DD + kt + a_c0, sz0);
        cp16z(dA1 + 4608u*2u, Al + (size_t)ca1 * DD + kt + a_c0, sz1);
        #pragma unroll
        for (int rr = 0; rr < 4; rr++) {
            int br = b_r0 + rr * 16;
            cp16(base + (9216u + (uint)(br * B_PITCH + b_c0)) * 2u,
                 Bh + (size_t)(kt + br) * DD + col0 + b_c0);
        }
    };

    float acc[2][4][4] = {};
    issue(0, 0);   cp_commit();
    issue(1, 64);  cp_commit();

    #pragma unroll
    for (int i = 0; i < 4; i++) {
        if (i < 3) asm volatile("cp.async.wait_group 1;");
        else       asm volatile("cp.async.wait_group 0;");
        __syncthreads();

        int st = i & 1;
        uint base = sbase + (uint)(st * STG_ELEMS) * 2u;
        uint aAh = base, aAl = base + 4608u * 2u;
        uint aBh = base + 9216u * 2u;

        #pragma unroll
        for (int ks = 0; ks < 64; ks += 16) {
            int arow = lane & 15;
            int kcol = ks + ((lane >> 4) << 3);
            uint ah[2][4], al[2][4];
            #pragma unroll
            for (int mi = 0; mi < 2; mi++) {
                uint off = (uint)((wm * 32 + mi * 16 + arow) * A_PITCH64 + kcol) * 2u;
                ldsm4(ah[mi][0], ah[mi][1], ah[mi][2], ah[mi][3], aAh + off);
                ldsm4(al[mi][0], al[mi][1], al[mi][2], al[mi][3], aAl + off);
            }
            uint bhf[2][4];
            int brow = ks + (lane & 15);
            #pragma unroll
            for (int ng = 0; ng < 2; ng++) {
                int bcol = wn * 32 + ng * 16 + ((lane >> 4) << 3);
                uint off = (uint)(brow * B_PITCH + bcol) * 2u;
                ldsm4t(bhf[ng][0], bhf[ng][1], bhf[ng][2], bhf[ng][3], aBh + off);
            }
            #pragma unroll
            for (int mi = 0; mi < 2; mi++)
                #pragma unroll
                for (int ng = 0; ng < 2; ng++) {
                    mma_bf16(acc[mi][ng * 2],     ah[mi], bhf[ng][0], bhf[ng][1]);
                    mma_bf16(acc[mi][ng * 2 + 1], ah[mi], bhf[ng][2], bhf[ng][3]);
                }
            #pragma unroll
            for (int mi = 0; mi < 2; mi++)
                #pragma unroll
                for (int ng = 0; ng < 2; ng++) {
                    mma_bf16(acc[mi][ng * 2],     al[mi], bhf[ng][0], bhf[ng][1]);
                    mma_bf16(acc[mi][ng * 2 + 1], al[mi], bhf[ng][2], bhf[ng][3]);
                }
        }
        __syncthreads();
        if (i < 2) { issue(st, (i + 2) * 64); cp_commit(); }
    }

    int grp = lane >> 2, q = lane & 3;
    #pragma unroll
    for (int mi = 0; mi < 2; mi++) {
        int rb = row0 + wm * 32 + mi * 16 + grp;
        #pragma unroll
        for (int nj = 0; nj < 4; nj++) {
            int cb = col0 + wn * 32 + nj * 8 + q * 2;
            float v0 = acc[mi][nj][0], v1 = acc[mi][nj][1];
            float v2 = acc[mi][nj][2], v3 = acc[mi][nj][3];
            if (bias) {
                float b0 = bias[cb], b1 = bias[cb + 1];
                size_t o0 = (size_t)rb * DD + cb;
                size_t o1 = (size_t)(rb + 8) * DD + cb;
                float r00 = 0.f, r01 = 0.f, r10 = 0.f, r11 = 0.f;
                if (rb < NN) {
                    float2 a2 = __bfloat1622float2(*(const __nv_bfloat162*)(rhh + o0));
                    float2 b2 = __bfloat1622float2(*(const __nv_bfloat162*)(rhl + o0));
                    r00 = a2.x + b2.x; r01 = a2.y + b2.y;
                }
                if (rb + 8 < NN) {
                    float2 a2 = __bfloat1622float2(*(const __nv_bfloat162*)(rhh + o1));
                    float2 b2 = __bfloat1622float2(*(const __nv_bfloat162*)(rhl + o1));
                    r10 = a2.x + b2.x; r11 = a2.y + b2.y;
                }
                v0 = fmaxf(v0 + b0 + r00, 0.f);
                v1 = fmaxf(v1 + b1 + r01, 0.f);
                v2 = fmaxf(v2 + b0 + r10, 0.f);
                v3 = fmaxf(v3 + b1 + r11, 0.f);
            }
            if (rb < NN) {
                size_t o = (size_t)rb * DD + cb;
                if (f32_out) { f32_out[o] = v0; f32_out[o + 1] = v1; }
                if (Chi) {
                    bf16 h0, l0, h1, l1;
                    f32split(v0, h0, l0); f32split(v1, h1, l1);
                    Chi[o] = h0; Chi[o + 1] = h1;
                    Clo[o] = l0; Clo[o + 1] = l1;
                }
            }
            if (rb + 8 < NN) {
                size_t o = (size_t)(rb + 8) * DD + cb;
                if (f32_out) { f32_out[o] = v2; f32_out[o + 1] = v3; }
                if (Chi) {
                    bf16 h2, l2, h3, l3;
                    f32split(v2, h2, l2); f32split(v3, h3, l3);
                    Chi[o] = h2; Chi[o + 1] = h3;
                    Clo[o] = l2; Clo[o + 1] = l3;
                }
            }
        }
    }
}

// ---------------- per-node online-softmax h-aggregation -------------------------
__global__ __launch_bounds__(256) void k_edge(
    const bf16* __restrict__ hhin,
    bf16* __restrict__ agg_hi, bf16* __restrict__ agg_lo)
{
    int gw = (blockIdx.x * blockDim.x + threadIdx.x) >> 5;
    int lane = threadIdx.x & 31;
    if (gw >= NN) return;
    int n = gw;
    int c0 = lane * 8;

    float t8[8];
    *(float4*)&t8[0] = *(const float4*)(g_t + (size_t)n * DD + c0);
    *(float4*)&t8[4] = *(const float4*)(g_t + (size_t)n * DD + c0 + 4);

    float m = -INFINITY, s = 0.f;
    float acc[8] = {};

    int e0 = g_off[n], e1 = g_off[n + 1];
    uint4 hv0, hv1;
    if (e0 < e1) {
        int sN = g_srcs[e0];
        hv0 = *(const uint4*)(hhin + (size_t)sN * DD + c0);
    }
    if (e0 + 1 < e1) {
        int sN = g_srcs[e0 + 1];
        hv1 = *(const uint4*)(hhin + (size_t)sN * DD + c0);
    }
    for (int e = e0; e < e1; e++) {
        uint4 hv = hv0;
        hv0 = hv1;
        if (e + 2 < e1) {
            int sN = g_srcs[e + 2];
            hv1 = *(const uint4*)(hhin + (size_t)sN * DD + c0);
        }

        const __nv_bfloat162* hp = (const __nv_bfloat162*)&hv;
        float hf[8];
        #pragma unroll
        for (int j = 0; j < 4; j++) {
            float2 f = __bfloat1622float2(hp[j]);
            hf[2 * j] = f.x; hf[2 * j + 1] = f.y;
        }
        float d = 0.f;
        #pragma unroll
        for (int j = 0; j < 8; j++) d += t8[j] * hf[j];
        #pragma unroll
        for (int o = 16; o > 0; o >>= 1) d += __shfl_xor_sync(0xffffffffu, d, o);
        d *= 0.0625f;

        float nm = fmaxf(m, d);
        float c = __expf(m - nm);
        float w = __expf(d - nm);
        s = s * c + w;
        m = nm;

        #pragma unroll
        for (int j = 0; j < 8; j++)
            acc[j] = acc[j] * c + w * hf[j];
    }

    float inv = 1.0f / (s + 1e-9f);
    bf16 hh8[8], hl8[8];
    #pragma unroll
    for (int j = 0; j < 8; j++) f32split(acc[j] * inv, hh8[j], hl8[j]);
    *(uint4*)(agg_hi + (size_t)n * DD + c0) = *(uint4*)&hh8[0];
    *(uint4*)(agg_lo + (size_t)n * DD + c0) = *(uint4*)&hl8[0];
}

// ---------------- launch ----------------------------------------------------------
extern "C" void kernel_launch(void* const* d_in, const int* in_sizes, int n_in,
                              void* d_out, int out_size)
{
    const float* x    = (const float*)d_in[0];
    const int*   edges= (const int*)  d_in[1];
    const float* w_in = (const float*)d_in[2];
    const float* b_in = (const float*)d_in[3];
    const float* wq   = (const float*)d_in[4];
    const float* wk   = (const float*)d_in[5];
    const float* wv   = (const float*)d_in[6];
    const float* wp   = (const float*)d_in[7];
    const float* bp   = (const float*)d_in[8];
    float* out = (float*)d_out;

    const int* src = edges;
    const int* dst = edges + NE;

    float *pt;
    bf16 *pxh, *pxl, *phhA, *phlA, *phhB, *phlB, *pwinh, *pwinl, *pMh, *pWh;
    cudaGetSymbolAddress((void**)&pt,    g_t);
    cudaGetSymbolAddress((void**)&pxh,   g_xh);
    cudaGetSymbolAddress((void**)&pxl,   g_xl);
    cudaGetSymbolAddress((void**)&phhA,  g_hhA);
    cudaGetSymbolAddress((void**)&phlA,  g_hlA);
    cudaGetSymbolAddress((void**)&phhB,  g_hhB);
    cudaGetSymbolAddress((void**)&phlB,  g_hlB);
    cudaGetSymbolAddress((void**)&pwinh, g_winh);
    cudaGetSymbolAddress((void**)&pwinl, g_winl);
    cudaGetSymbolAddress((void**)&pMh,   g_Mh);
    cudaGetSymbolAddress((void**)&pWh,   g_Wh);

    static cudaStream_t s_side = nullptr;
    static cudaEvent_t s_ev0 = nullptr, s_evFold = nullptr, s_evCsr = nullptr;
    if (!s_side) {
        cudaFuncSetAttribute(k_mma_h0, cudaFuncAttributeMaxDynamicSharedMemorySize,
                             3 * STH_ELEMS * 2);
        cudaFuncSetAttribute(k_gemm, cudaFuncAttributeMaxDynamicSharedMemorySize,
                             2 * STG_ELEMS * 2);
        cudaStreamCreateWithFlags(&s_side, cudaStreamNonBlocking);
        cudaEventCreateWithFlags(&s_ev0, cudaEventDisableTiming);
        cudaEventCreateWithFlags(&s_evFold, cudaEventDisableTiming);
        cudaEventCreateWithFlags(&s_evCsr, cudaEventDisableTiming);
    }

    dim3 gw(2, 157);   // 64-row tiles

    // ---- fork: weight folding + CSR on side stream
    cudaEventRecord(s_ev0, 0);
    cudaStreamWaitEvent(s_side, s_ev0, 0);
    k_small    <<<dim3(4, 4, 6), 256, 0, s_side>>>(wq, wk, wv, wp, pMh, pWh);
    cudaEventRecord(s_evFold, s_side);
    k_init     <<<(NN + 255) / 256, 256, 0, s_side>>>();
    k_hist     <<<(NE + 255) / 256, 256, 0, s_side>>>(dst);
    k_scan_part<<<40, 256, 0, s_side>>>();
    k_scan_top <<<1, 64, 0, s_side>>>();
    k_scan_add <<<40, 256, 0, s_side>>>();
    k_scatter  <<<(NE + 255) / 256, 256, 0, s_side>>>(src, dst);
    cudaEventRecord(s_evCsr, s_side);

    // ---- main stream: conversions + h0 GEMM
    k_cvt2<<<(NN * DD + DD * DD + 255) / 256, 256>>>(
        x, pxh, pxl, NN * DD, w_in, pwinh, pwinl, DD * DD);
    k_mma_h0<<<gw, 256, 3 * STH_ELEMS * 2>>>(
        pxh, pxl, pwinh, pwinl, b_in, phhA, phlA);

    // join 1: t-GEMM needs folded weights only
    cudaStreamWaitEvent(0, s_evFold, 0);

    bf16* paggh = pxh;   // agg buffers reuse x hi/lo
    bf16* paggl = pxl;

    bf16* chh = phhA; bf16* chl = phlA;
    bf16* nhh = phhB; bf16* nhl = phlB;
    for (int l = 0; l < NL; l++) {
        // t = h @ M (fp32 out)
        k_gemm<<<gw, 256, 2 * STG_ELEMS * 2>>>(
            chh, chl, pMh + l * DD * DD, pt,
            nullptr, nullptr, nullptr, nullptr, nullptr);
        // join 2 (first layer only): edge needs CSR
        if (l == 0) cudaStreamWaitEvent(0, s_evCsr, 0);
        // edge: aggregate h with softmax weights
        k_edge<<<(NN * 32 + 255) / 256, 256>>>(chh, paggh, paggl);
        // p GEMM: hnext = relu(agg @ wvp + bp + h)
        float* ho = (l == NL - 1) ? out : nullptr;
        bf16* oh = (l == NL - 1) ? nullptr : nhh;
        bf16* ol = (l == NL - 1) ? nullptr : nhl;
        k_gemm<<<gw, 256, 2 * STG_ELEMS * 2>>>(
            paggh, paggl, pWh + l * DD * DD, ho,
            bp + l * DD, chh, chl, oh, ol);
        bf16* t1 = chh; chh = nhh; nhh = t1;
        bf16* t2 = chl; chl = nhl; nhl = t2;
    }
}

// round 14
// speedup vs baseline: 1.4297x; 1.0226x over previous
#include <cuda_runtime.h>
#include <cuda_bf16.h>
#include <stdint.h>
#include <math.h>

#define NN 10000
#define NE 320000
#define DD 256
#define NL 3

typedef __nv_bfloat16 bf16;
typedef unsigned int uint;

// ---------------- scratch -----------------------------------------------------
__device__ float g_t[NN * DD];
__device__ bf16  g_xh[NN * DD], g_xl[NN * DD];          // x hi/lo, reused as agg hi/lo
__device__ bf16  g_hhA[NN * DD], g_hlA[NN * DD];
__device__ bf16  g_hhB[NN * DD], g_hlB[NN * DD];
__device__ bf16  g_winh[DD * DD], g_winl[DD * DD];
__device__ bf16  g_Mh[NL * DD * DD];                    // wq wk^T (bf16 hi)
__device__ bf16  g_Wh[NL * DD * DD];                    // wv wp   (bf16 hi)
__device__ int   g_deg[NN];
__device__ int   g_off[NN + 1];
__device__ int   g_cur[NN];
__device__ int   g_bt[40];
__device__ int   g_srcs[NE];

// ---------------- helpers -----------------------------------------------------
__device__ __forceinline__ void f32split(float v, bf16& h, bf16& l) {
    h = __float2bfloat16(v);
    l = __float2bfloat16(v - __bfloat162float(h));
}
__device__ __forceinline__ void ldsm4(uint& r0, uint& r1, uint& r2, uint& r3, uint addr) {
    asm volatile("ldmatrix.sync.aligned.m8n8.x4.shared.b16 {%0,%1,%2,%3}, [%4];"
                 : "=r"(r0), "=r"(r1), "=r"(r2), "=r"(r3) : "r"(addr));
}
__device__ __forceinline__ void ldsm4t(uint& r0, uint& r1, uint& r2, uint& r3, uint addr) {
    asm volatile("ldmatrix.sync.aligned.m8n8.x4.trans.shared.b16 {%0,%1,%2,%3}, [%4];"
                 : "=r"(r0), "=r"(r1), "=r"(r2), "=r"(r3) : "r"(addr));
}
__device__ __forceinline__ void mma_bf16(float* c, const uint* a, uint b0, uint b1) {
    asm volatile("mma.sync.aligned.m16n8k16.row.col.f32.bf16.bf16.f32 "
                 "{%0,%1,%2,%3},{%4,%5,%6,%7},{%8,%9},{%0,%1,%2,%3};"
                 : "+f"(c[0]), "+f"(c[1]), "+f"(c[2]), "+f"(c[3])
                 : "r"(a[0]), "r"(a[1]), "r"(a[2]), "r"(a[3]), "r"(b0), "r"(b1));
}
__device__ __forceinline__ void cp16(uint dst, const void* src) {
    asm volatile("cp.async.cg.shared.global [%0], [%1], 16;" :: "r"(dst), "l"(src));
}
__device__ __forceinline__ void cp16z(uint dst, const void* src, uint sz) {
    asm volatile("cp.async.cg.shared.global [%0], [%1], 16, %2;" :: "r"(dst), "l"(src), "r"(sz));
}
__device__ __forceinline__ void cp_commit() { asm volatile("cp.async.commit_group;"); }

// ---------------- CSR build ----------------------------------------------------
__global__ void k_init() {
    int i = blockIdx.x * blockDim.x + threadIdx.x;
    if (i < NN) { g_deg[i] = 0; g_cur[i] = 0; }
}
__global__ void k_hist(const int* __restrict__ dst) {
    int e = blockIdx.x * blockDim.x + threadIdx.x;
    if (e < NE) atomicAdd(&g_deg[dst[e]], 1);
}
__global__ __launch_bounds__(256) void k_scan_part() {
    __shared__ int ws[8];
    int b = blockIdx.x, tid = threadIdx.x;
    int lane = tid & 31, wid = tid >> 5;
    int i = b * 256 + tid;
    int x = (i < NN) ? g_deg[i] : 0;
    int v = x;
    #pragma unroll
    for (int o = 1; o < 32; o <<= 1) {
        int y = __shfl_up_sync(0xffffffffu, v, o);
        if (lane >= o) v += y;
    }
    if (lane == 31) ws[wid] = v;
    __syncthreads();
    if (tid < 8) {
        int w = ws[tid];
        #pragma unroll
        for (int o = 1; o < 8; o <<= 1) {
            int y = __shfl_up_sync(0xffu, w, o);
            if (tid >= o) w += y;
        }
        ws[tid] = w;
    }
    __syncthreads();
    int add = wid ? ws[wid - 1] : 0;
    if (i < NN) g_off[i] = add + v - x;
    if (tid == 255) g_bt[b] = add + v;
}
__global__ void k_scan_top() {
    int tid = threadIdx.x;
    int v = (tid < 40) ? g_bt[tid] : 0;
    int e = v;
    #pragma unroll
    for (int o = 1; o < 64; o <<= 1) {
        int y = __shfl_up_sync(0xffffffffu, e, o);
        if ((threadIdx.x & 31) >= o) e += y;
    }
    __shared__ int carry;
    if (tid == 31) carry = e;
    __syncthreads();
    if (tid < 40) {
        int ex = e - v + ((tid >= 32) ? carry : 0);
        g_bt[tid] = ex;
    }
    if (tid == 0) g_off[NN] = NE;
}
__global__ __launch_bounds__(256) void k_scan_add() {
    int b = blockIdx.x;
    int i = b * 256 + threadIdx.x;
    if (b > 0 && i < NN) g_off[i] += g_bt[b];
}
__global__ void k_scatter(const int* __restrict__ src, const int* __restrict__ dst) {
    int e = blockIdx.x * blockDim.x + threadIdx.x;
    if (e < NE) {
        int d = dst[e];
        int pos = g_off[d] + atomicAdd(&g_cur[d], 1);
        g_srcs[pos] = src[e];
    }
}

// ---------------- fused fp32 -> bf16 hi/lo, vectorized x4 ------------------------
__global__ void k_cvt2(const float4* __restrict__ a4, bf16* __restrict__ ah,
                       bf16* __restrict__ al, int na4,
                       const float4* __restrict__ b4, bf16* __restrict__ bh,
                       bf16* __restrict__ bl, int nb4) {
    int i = blockIdx.x * blockDim.x + threadIdx.x;
    if (i < na4) {
        float4 v = a4[i];
        bf16 h4[4], l4[4];
        f32split(v.x, h4[0], l4[0]); f32split(v.y, h4[1], l4[1]);
        f32split(v.z, h4[2], l4[2]); f32split(v.w, h4[3], l4[3]);
        *(uint2*)(ah + i * 4) = *(uint2*)h4;
        *(uint2*)(al + i * 4) = *(uint2*)l4;
    } else if (i < na4 + nb4) {
        int j = i - na4;
        float4 v = b4[j];
        bf16 h4[4], l4[4];
        f32split(v.x, h4[0], l4[0]); f32split(v.y, h4[1], l4[1]);
        f32split(v.z, h4[2], l4[2]); f32split(v.w, h4[3], l4[3]);
        *(uint2*)(bh + j * 4) = *(uint2*)h4;
        *(uint2*)(bl + j * 4) = *(uint2*)l4;
    }
}

// ---------------- weight folding (bf16-hi outputs) -------------------------------
__global__ __launch_bounds__(256) void k_small(
    const float* __restrict__ wq, const float* __restrict__ wk,
    const float* __restrict__ wv, const float* __restrict__ wp,
    bf16* __restrict__ pMh, bf16* __restrict__ pWh)
{
    int z = blockIdx.z;
    const float* A; const float* B; bf16* Ch; int tb;
    if (z < 3) { A = wq + z * DD * DD; B = wk + z * DD * DD;
                 Ch = pMh + z * DD * DD; tb = 1; }
    else       { A = wv + (z - 3) * DD * DD; B = wp + (z - 3) * DD * DD;
                 Ch = pWh + (z - 3) * DD * DD; tb = 0; }

    __shared__ float As[16][65];
    __shared__ float Bs[16][65];
    int tid = threadIdx.x;
    int tx = tid & 15, ty = tid >> 4;
    int row0 = blockIdx.y * 64, col0 = blockIdx.x * 64;
    float acc[4][4] = {};

    for (int kt = 0; kt < DD; kt += 16) {
        {
            int r = tid >> 2, c = (tid & 3) * 4;
            float4 v = *(const float4*)(A + (row0 + r) * DD + kt + c);
            As[c + 0][r] = v.x; As[c + 1][r] = v.y; As[c + 2][r] = v.z; As[c + 3][r] = v.w;
        }
        if (tb) {
            int c = tid >> 2, k = (tid & 3) * 4;
            float4 v = *(const float4*)(B + (col0 + c) * DD + kt + k);
            Bs[k + 0][c] = v.x; Bs[k + 1][c] = v.y; Bs[k + 2][c] = v.z; Bs[k + 3][c] = v.w;
        } else {
            int k = tid >> 4, c = (tid & 15) * 4;
            float4 v = *(const float4*)(B + (kt + k) * DD + col0 + c);
            Bs[k][c + 0] = v.x; Bs[k][c + 1] = v.y; Bs[k][c + 2] = v.z; Bs[k][c + 3] = v.w;
        }
        __syncthreads();
        #pragma unroll
        for (int kk = 0; kk < 16; kk++) {
            float a[4], b[4];
            #pragma unroll
            for (int i = 0; i < 4; i++) { a[i] = As[kk][ty * 4 + i]; b[i] = Bs[kk][tx * 4 + i]; }
            #pragma unroll
            for (int i = 0; i < 4; i++)
                #pragma unroll
                for (int j = 0; j < 4; j++)
                    acc[i][j] += a[i] * b[j];
        }
        __syncthreads();
    }
    #pragma unroll
    for (int i = 0; i < 4; i++)
        #pragma unroll
        for (int j = 0; j < 4; j++)
            Ch[(row0 + ty * 4 + i) * DD + col0 + tx * 4 + j] = __float2bfloat16(acc[i][j]);
}

// ---------------- h0 GEMM: 64x128 tile, 3 products, occ 2 -----------------------
#define STH_ELEMS 13824
#define A_PITCH 40
#define B_PITCH 136

__global__ __launch_bounds__(256, 2) void k_mma_h0(
    const bf16* __restrict__ Ah, const bf16* __restrict__ Al,
    const bf16* __restrict__ Bh, const bf16* __restrict__ Bl,
    const float* __restrict__ bias,
    bf16* __restrict__ Chi, bf16* __restrict__ Clo)
{
    extern __shared__ __align__(16) bf16 smem[];
    int tid = threadIdx.x;
    int lane = tid & 31, warp = tid >> 5;
    int wm = warp & 1, wn = warp >> 1;
    int row0 = blockIdx.y * 64, col0 = blockIdx.x * 128;

    uint sbase = (uint)__cvta_generic_to_shared(smem);
    int a_r0 = tid >> 2,        a_c0 = (tid & 3) * 8;
    int b_r0 = tid >> 4,        b_c0 = (tid & 15) * 8;
    int b_r1 = (tid + 256) >> 4;

    int ga0 = row0 + a_r0;
    uint sz0 = (ga0 < NN) ? 16u : 0u;
    int ca0 = (ga0 < NN) ? ga0 : 0;

    auto issue = [&](int st, int kt) {
        uint base = sbase + (uint)(st * STH_ELEMS) * 2u;
        uint dA0 = base + (uint)(a_r0 * A_PITCH + a_c0) * 2u;
        cp16z(dA0,            Ah + (size_t)ca0 * DD + kt + a_c0, sz0);
        cp16z(dA0 + 2560u*2u, Al + (size_t)ca0 * DD + kt + a_c0, sz0);
        uint dB0 = base + (5120u + (uint)(b_r0 * B_PITCH + b_c0)) * 2u;
        uint dB1 = base + (5120u + (uint)(b_r1 * B_PITCH + b_c0)) * 2u;
        cp16(dB0, Bh + (size_t)(kt + b_r0) * DD + col0 + b_c0);
        cp16(dB1, Bh + (size_t)(kt + b_r1) * DD + col0 + b_c0);
        cp16(dB0 + 4352u*2u, Bl + (size_t)(kt + b_r0) * DD + col0 + b_c0);
        cp16(dB1 + 4352u*2u, Bl + (size_t)(kt + b_r1) * DD + col0 + b_c0);
    };

    float acc[2][4][4] = {};
    issue(0, 0);   cp_commit();
    issue(1, 32);  cp_commit();

    #pragma unroll
    for (int i = 0; i < 8; i++) {
        if (i < 7) asm volatile("cp.async.wait_group 1;");
        else       asm volatile("cp.async.wait_group 0;");
        __syncthreads();
        if (i < 6) { issue((i + 2) % 3, (i + 2) * 32); cp_commit(); }

        int st = i % 3;
        uint base = sbase + (uint)(st * STH_ELEMS) * 2u;
        uint aAh = base, aAl = base + 2560u * 2u;
        uint aBh = base + 5120u * 2u, aBl = base + 9472u * 2u;

        #pragma unroll
        for (int ks = 0; ks < 32; ks += 16) {
            int arow = lane & 15;
            int kcol = ks + ((lane >> 4) << 3);
            uint ah[2][4], al[2][4];
            #pragma unroll
            for (int mi = 0; mi < 2; mi++) {
                uint off = (uint)((wm * 32 + mi * 16 + arow) * A_PITCH + kcol) * 2u;
                ldsm4(ah[mi][0], ah[mi][1], ah[mi][2], ah[mi][3], aAh + off);
                ldsm4(al[mi][0], al[mi][1], al[mi][2], al[mi][3], aAl + off);
            }
            uint bhf[2][4], blf[2][4];
            int brow = ks + (lane & 15);
            #pragma unroll
            for (int ng = 0; ng < 2; ng++) {
                int bcol = wn * 32 + ng * 16 + ((lane >> 4) << 3);
                uint off = (uint)(brow * B_PITCH + bcol) * 2u;
                ldsm4t(bhf[ng][0], bhf[ng][1], bhf[ng][2], bhf[ng][3], aBh + off);
                ldsm4t(blf[ng][0], blf[ng][1], blf[ng][2], blf[ng][3], aBl + off);
            }
            #pragma unroll
            for (int mi = 0; mi < 2; mi++)
                #pragma unroll
                for (int ng = 0; ng < 2; ng++) {
                    mma_bf16(acc[mi][ng * 2],     ah[mi], bhf[ng][0], bhf[ng][1]);
                    mma_bf16(acc[mi][ng * 2 + 1], ah[mi], bhf[ng][2], bhf[ng][3]);
                }
            #pragma unroll
            for (int mi = 0; mi < 2; mi++)
                #pragma unroll
                for (int ng = 0; ng < 2; ng++) {
                    mma_bf16(acc[mi][ng * 2],     al[mi], bhf[ng][0], bhf[ng][1]);
                    mma_bf16(acc[mi][ng * 2 + 1], al[mi], bhf[ng][2], bhf[ng][3]);
                }
            #pragma unroll
            for (int mi = 0; mi < 2; mi++)
                #pragma unroll
                for (int ng = 0; ng < 2; ng++) {
                    mma_bf16(acc[mi][ng * 2],     ah[mi], blf[ng][0], blf[ng][1]);
                    mma_bf16(acc[mi][ng * 2 + 1], ah[mi], blf[ng][2], blf[ng][3]);
                }
        }
    }

    int grp = lane >> 2, q = lane & 3;
    #pragma unroll
    for (int mi = 0; mi < 2; mi++) {
        int rb = row0 + wm * 32 + mi * 16 + grp;
        #pragma unroll
        for (int nj = 0; nj < 4; nj++) {
            int cb = col0 + wn * 32 + nj * 8 + q * 2;
            float b0 = bias[cb], b1 = bias[cb + 1];
            float v0 = fmaxf(acc[mi][nj][0] + b0, 0.f);
            float v1 = fmaxf(acc[mi][nj][1] + b1, 0.f);
            float v2 = fmaxf(acc[mi][nj][2] + b0, 0.f);
            float v3 = fmaxf(acc[mi][nj][3] + b1, 0.f);
            if (rb < NN) {
                size_t o = (size_t)rb * DD + cb;
                bf16 h0, l0, h1, l1;
                f32split(v0, h0, l0); f32split(v1, h1, l1);
                Chi[o] = h0; Chi[o + 1] = h1;
                Clo[o] = l0; Clo[o + 1] = l1;
            }
            if (rb + 8 < NN) {
                size_t o = (size_t)(rb + 8) * DD + cb;
                bf16 h2, l2, h3, l3;
                f32split(v2, h2, l2); f32split(v3, h3, l3);
                Chi[o] = h2; Chi[o + 1] = h3;
                Clo[o] = l2; Clo[o + 1] = l3;
            }
        }
    }
}

// ---------------- unified 2-product GEMM, 64x128 tile, K32, occ 3 ---------------
#define STG_ELEMS 9472

__global__ __launch_bounds__(256, 3) void k_gemm(
    const bf16* __restrict__ Ah, const bf16* __restrict__ Al,
    const bf16* __restrict__ Bh,
    float* __restrict__ f32_out, const float* __restrict__ bias,
    const bf16* __restrict__ rhh, const bf16* __restrict__ rhl,
    bf16* __restrict__ Chi, bf16* __restrict__ Clo)
{
    extern __shared__ __align__(16) bf16 smem[];
    int col0 = blockIdx.x * 128;
    int row0 = blockIdx.y * 64;

    int tid = threadIdx.x;
    int lane = tid & 31, warp = tid >> 5;
    int wm = warp & 1, wn = warp >> 1;

    uint sbase = (uint)__cvta_generic_to_shared(smem);
    int a_r0 = tid >> 2,        a_c0 = (tid & 3) * 8;
    int b_r0 = tid >> 4,        b_c0 = (tid & 15) * 8;
    int b_r1 = (tid + 256) >> 4;

    int ga0 = row0 + a_r0;
    uint sz0 = (ga0 < NN) ? 16u : 0u;
    int ca0 = (ga0 < NN) ? ga0 : 0;

    auto issue = [&](int st, int kt) {
        uint base = sbase + (uint)(st * STG_ELEMS) * 2u;
        uint dA0 = base + (uint)(a_r0 * A_PITCH + a_c0) * 2u;
        cp16z(dA0,            Ah + (size_t)ca0 * DD + kt + a_c0, sz0);
        cp16z(dA0 + 2560u*2u, Al + (size_t)ca0 * DD + kt + a_c0, sz0);
        uint dB0 = base + (5120u + (uint)(b_r0 * B_PITCH + b_c0)) * 2u;
        uint dB1 = base + (5120u + (uint)(b_r1 * B_PITCH + b_c0)) * 2u;
        cp16(dB0, Bh + (size_t)(kt + b_r0) * DD + col0 + b_c0);
        cp16(dB1, Bh + (size_t)(kt + b_r1) * DD + col0 + b_c0);
    };

    float acc[2][4][4] = {};
    issue(0, 0);   cp_commit();
    issue(1, 32);  cp_commit();

    #pragma unroll
    for (int i = 0; i < 8; i++) {
        if (i < 7) asm volatile("cp.async.wait_group 1;");
        else       asm volatile("cp.async.wait_group 0;");
        __syncthreads();
        if (i < 6) { issue((i + 2) % 3, (i + 2) * 32); cp_commit(); }

        int st = i % 3;
        uint base = sbase + (uint)(st * STG_ELEMS) * 2u;
        uint aAh = base, aAl = base + 2560u * 2u;
        uint aBh = base + 5120u * 2u;

        #pragma unroll
        for (int ks = 0; ks < 32; ks += 16) {
            int arow = lane & 15;
            int kcol = ks + ((lane >> 4) << 3);
            uint ah[2][4], al[2][4];
            #pragma unroll
            for (int mi = 0; mi < 2; mi++) {
                uint off = (uint)((wm * 32 + mi * 16 + arow) * A_PITCH + kcol) * 2u;
                ldsm4(ah[mi][0], ah[mi][1], ah[mi][2], ah[mi][3], aAh + off);
                ldsm4(al[mi][0], al[mi][1], al[mi][2], al[mi][3], aAl + off);
            }
            uint bhf[2][4];
            int brow = ks + (lane & 15);
            #pragma unroll
            for (int ng = 0; ng < 2; ng++) {
                int bcol = wn * 32 + ng * 16 + ((lane >> 4) << 3);
                uint off = (uint)(brow * B_PITCH + bcol) * 2u;
                ldsm4t(bhf[ng][0], bhf[ng][1], bhf[ng][2], bhf[ng][3], aBh + off);
            }
            #pragma unroll
            for (int mi = 0; mi < 2; mi++)
                #pragma unroll
                for (int ng = 0; ng < 2; ng++) {
                    mma_bf16(acc[mi][ng * 2],     ah[mi], bhf[ng][0], bhf[ng][1]);
                    mma_bf16(acc[mi][ng * 2 + 1], ah[mi], bhf[ng][2], bhf[ng][3]);
                }
            #pragma unroll
            for (int mi = 0; mi < 2; mi++)
                #pragma unroll
                for (int ng = 0; ng < 2; ng++) {
                    mma_bf16(acc[mi][ng * 2],     al[mi], bhf[ng][0], bhf[ng][1]);
                    mma_bf16(acc[mi][ng * 2 + 1], al[mi], bhf[ng][2], bhf[ng][3]);
                }
        }
    }

    int grp = lane >> 2, q = lane & 3;
    #pragma unroll
    for (int mi = 0; mi < 2; mi++) {
        int rb = row0 + wm * 32 + mi * 16 + grp;
        #pragma unroll
        for (int nj = 0; nj < 4; nj++) {
            int cb = col0 + wn * 32 + nj * 8 + q * 2;
            float v0 = acc[mi][nj][0], v1 = acc[mi][nj][1];
            float v2 = acc[mi][nj][2], v3 = acc[mi][nj][3];
            if (bias) {
                float b0 = bias[cb], b1 = bias[cb + 1];
                size_t o0 = (size_t)rb * DD + cb;
                size_t o1 = (size_t)(rb + 8) * DD + cb;
                float r00 = 0.f, r01 = 0.f, r10 = 0.f, r11 = 0.f;
                if (rb < NN) {
                    float2 a2 = __bfloat1622float2(*(const __nv_bfloat162*)(rhh + o0));
                    float2 b2 = __bfloat1622float2(*(const __nv_bfloat162*)(rhl + o0));
                    r00 = a2.x + b2.x; r01 = a2.y + b2.y;
                }
                if (rb + 8 < NN) {
                    float2 a2 = __bfloat1622float2(*(const __nv_bfloat162*)(rhh + o1));
                    float2 b2 = __bfloat1622float2(*(const __nv_bfloat162*)(rhl + o1));
                    r10 = a2.x + b2.x; r11 = a2.y + b2.y;
                }
                v0 = fmaxf(v0 + b0 + r00, 0.f);
                v1 = fmaxf(v1 + b1 + r01, 0.f);
                v2 = fmaxf(v2 + b0 + r10, 0.f);
                v3 = fmaxf(v3 + b1 + r11, 0.f);
            }
            if (rb < NN) {
                size_t o = (size_t)rb * DD + cb;
                if (f32_out) { f32_out[o] = v0; f32_out[o + 1] = v1; }
                if (Chi) {
                    bf16 h0, l0, h1, l1;
                    f32split(v0, h0, l0); f32split(v1, h1, l1);
                    Chi[o] = h0; Chi[o + 1] = h1;
                    Clo[o] = l0; Clo[o + 1] = l1;
                }
            }
            if (rb + 8 < NN) {
                size_t o = (size_t)(rb + 8) * DD + cb;
                if (f32_out) { f32_out[o] = v2; f32_out[o + 1] = v3; }
                if (Chi) {
                    bf16 h2, l2, h3, l3;
                    f32split(v2, h2, l2); f32split(v3, h3, l3);
                    Chi[o] = h2; Chi[o + 1] = h3;
                    Clo[o] = l2; Clo[o + 1] = l3;
                }
            }
        }
    }
}

// ---------------- per-node online-softmax h-aggregation -------------------------
__global__ __launch_bounds__(256) void k_edge(
    const bf16* __restrict__ hhin,
    bf16* __restrict__ agg_hi, bf16* __restrict__ agg_lo)
{
    int gw = (blockIdx.x * blockDim.x + threadIdx.x) >> 5;
    int lane = threadIdx.x & 31;
    if (gw >= NN) return;
    int n = gw;
    int c0 = lane * 8;

    float t8[8];
    *(float4*)&t8[0] = *(const float4*)(g_t + (size_t)n * DD + c0);
    *(float4*)&t8[4] = *(const float4*)(g_t + (size_t)n * DD + c0 + 4);

    float m = -INFINITY, s = 0.f;
    float acc[8] = {};

    int e0 = g_off[n], e1 = g_off[n + 1];
    uint4 hv0, hv1;
    if (e0 < e1) {
        int sN = g_srcs[e0];
        hv0 = *(const uint4*)(hhin + (size_t)sN * DD + c0);
    }
    if (e0 + 1 < e1) {
        int sN = g_srcs[e0 + 1];
        hv1 = *(const uint4*)(hhin + (size_t)sN * DD + c0);
    }
    for (int e = e0; e < e1; e++) {
        uint4 hv = hv0;
        hv0 = hv1;
        if (e + 2 < e1) {
            int sN = g_srcs[e + 2];
            hv1 = *(const uint4*)(hhin + (size_t)sN * DD + c0);
        }

        const __nv_bfloat162* hp = (const __nv_bfloat162*)&hv;
        float hf[8];
        #pragma unroll
        for (int j = 0; j < 4; j++) {
            float2 f = __bfloat1622float2(hp[j]);
            hf[2 * j] = f.x; hf[2 * j + 1] = f.y;
        }
        float d = 0.f;
        #pragma unroll
        for (int j = 0; j < 8; j++) d += t8[j] * hf[j];
        #pragma unroll
        for (int o = 16; o > 0; o >>= 1) d += __shfl_xor_sync(0xffffffffu, d, o);
        d *= 0.0625f;

        float nm = fmaxf(m, d);
        float c = __expf(m - nm);
        float w = __expf(d - nm);
        s = s * c + w;
        m = nm;

        #pragma unroll
        for (int j = 0; j < 8; j++)
            acc[j] = acc[j] * c + w * hf[j];
    }

    float inv = 1.0f / (s + 1e-9f);
    bf16 hh8[8], hl8[8];
    #pragma unroll
    for (int j = 0; j < 8; j++) f32split(acc[j] * inv, hh8[j], hl8[j]);
    *(uint4*)(agg_hi + (size_t)n * DD + c0) = *(uint4*)&hh8[0];
    *(uint4*)(agg_lo + (size_t)n * DD + c0) = *(uint4*)&hl8[0];
}

// ---------------- launch ----------------------------------------------------------
extern "C" void kernel_launch(void* const* d_in, const int* in_sizes, int n_in,
                              void* d_out, int out_size)
{
    const float* x    = (const float*)d_in[0];
    const int*   edges= (const int*)  d_in[1];
    const float* w_in = (const float*)d_in[2];
    const float* b_in = (const float*)d_in[3];
    const float* wq   = (const float*)d_in[4];
    const float* wk   = (const float*)d_in[5];
    const float* wv   = (const float*)d_in[6];
    const float* wp   = (const float*)d_in[7];
    const float* bp   = (const float*)d_in[8];
    float* out = (float*)d_out;

    const int* src = edges;
    const int* dst = edges + NE;

    float *pt;
    bf16 *pxh, *pxl, *phhA, *phlA, *phhB, *phlB, *pwinh, *pwinl, *pMh, *pWh;
    cudaGetSymbolAddress((void**)&pt,    g_t);
    cudaGetSymbolAddress((void**)&pxh,   g_xh);
    cudaGetSymbolAddress((void**)&pxl,   g_xl);
    cudaGetSymbolAddress((void**)&phhA,  g_hhA);
    cudaGetSymbolAddress((void**)&phlA,  g_hlA);
    cudaGetSymbolAddress((void**)&phhB,  g_hhB);
    cudaGetSymbolAddress((void**)&phlB,  g_hlB);
    cudaGetSymbolAddress((void**)&pwinh, g_winh);
    cudaGetSymbolAddress((void**)&pwinl, g_winl);
    cudaGetSymbolAddress((void**)&pMh,   g_Mh);
    cudaGetSymbolAddress((void**)&pWh,   g_Wh);

    static cudaStream_t s_side = nullptr;
    static cudaEvent_t s_ev0 = nullptr, s_evFold = nullptr, s_evCsr = nullptr;
    if (!s_side) {
        cudaFuncSetAttribute(k_mma_h0, cudaFuncAttributeMaxDynamicSharedMemorySize,
                             3 * STH_ELEMS * 2);
        cudaFuncSetAttribute(k_gemm, cudaFuncAttributeMaxDynamicSharedMemorySize,
                             3 * STG_ELEMS * 2);
        cudaStreamCreateWithFlags(&s_side, cudaStreamNonBlocking);
        cudaEventCreateWithFlags(&s_ev0, cudaEventDisableTiming);
        cudaEventCreateWithFlags(&s_evFold, cudaEventDisableTiming);
        cudaEventCreateWithFlags(&s_evCsr, cudaEventDisableTiming);
    }

    dim3 gw(2, 157);   // 64-row tiles

    // ---- fork: weight folding + CSR on side stream
    cudaEventRecord(s_ev0, 0);
    cudaStreamWaitEvent(s_side, s_ev0, 0);
    k_small    <<<dim3(4, 4, 6), 256, 0, s_side>>>(wq, wk, wv, wp, pMh, pWh);
    cudaEventRecord(s_evFold, s_side);
    k_init     <<<(NN + 255) / 256, 256, 0, s_side>>>();
    k_hist     <<<(NE + 255) / 256, 256, 0, s_side>>>(dst);
    k_scan_part<<<40, 256, 0, s_side>>>();
    k_scan_top <<<1, 64, 0, s_side>>>();
    k_scan_add <<<40, 256, 0, s_side>>>();
    k_scatter  <<<(NE + 255) / 256, 256, 0, s_side>>>(src, dst);
    cudaEventRecord(s_evCsr, s_side);

    // ---- main stream: conversions + h0 GEMM
    int na4 = NN * DD / 4, nb4 = DD * DD / 4;
    k_cvt2<<<(na4 + nb4 + 255) / 256, 256>>>(
        (const float4*)x, pxh, pxl, na4,
        (const float4*)w_in, pwinh, pwinl, nb4);
    k_mma_h0<<<gw, 256, 3 * STH_ELEMS * 2>>>(
        pxh, pxl, pwinh, pwinl, b_in, phhA, phlA);

    // join 1: t-GEMM needs folded weights only
    cudaStreamWaitEvent(0, s_evFold, 0);

    bf16* paggh = pxh;   // agg buffers reuse x hi/lo
    bf16* paggl = pxl;

    bf16* chh = phhA; bf16* chl = phlA;
    bf16* nhh = phhB; bf16* nhl = phlB;
    for (int l = 0; l < NL; l++) {
        // t = h @ M (fp32 out)
        k_gemm<<<gw, 256, 3 * STG_ELEMS * 2>>>(
            chh, chl, pMh + l * DD * DD, pt,
            nullptr, nullptr, nullptr, nullptr, nullptr);
        // join 2 (first layer only): edge needs CSR
        if (l == 0) cudaStreamWaitEvent(0, s_evCsr, 0);
        // edge: aggregate h with softmax weights
        k_edge<<<(NN * 32 + 255) / 256, 256>>>(chh, paggh, paggl);
        // p GEMM: hnext = relu(agg @ wvp + bp + h)
        float* ho = (l == NL - 1) ? out : nullptr;
        bf16* oh = (l == NL - 1) ? nullptr : nhh;
        bf16* ol = (l == NL - 1) ? nullptr : nhl;
        k_gemm<<<gw, 256, 3 * STG_ELEMS * 2>>>(
            paggh, paggl, pWh + l * DD * DD, ho,
            bp + l * DD, chh, chl, oh, ol);
        bf16* t1 = chh; chh = nhh; nhh = t1;
        bf16* t2 = chl; chl = nhl; nhl = t2;
    }
}

// round 15
// speedup vs baseline: 1.4937x; 1.0448x over previous
#include <cuda_runtime.h>
#include <cuda_bf16.h>
#include <stdint.h>
#include <math.h>

#define NN 10000
#define NE 320000
#define DD 256
#define NL 3

// row split: chain A = [0, 5056), chain B = [5056, 10000)
#define RSPLIT 5056

typedef __nv_bfloat16 bf16;
typedef unsigned int uint;

// ---------------- scratch -----------------------------------------------------
__device__ float g_t[NN * DD];
__device__ bf16  g_xh[NN * DD], g_xl[NN * DD];
__device__ bf16  g_hhA[NN * DD], g_hlA[NN * DD];
__device__ bf16  g_hhB[NN * DD], g_hlB[NN * DD];
__device__ bf16  g_winh[DD * DD], g_winl[DD * DD];
__device__ bf16  g_Mh[NL * DD * DD];
__device__ bf16  g_Wh[NL * DD * DD];
__device__ int   g_deg[NN];
__device__ int   g_off[NN + 1];
__device__ int   g_cur[NN];
__device__ int   g_bt[40];
__device__ int   g_srcs[NE];

// ---------------- helpers -----------------------------------------------------
__device__ __forceinline__ void f32split(float v, bf16& h, bf16& l) {
    h = __float2bfloat16(v);
    l = __float2bfloat16(v - __bfloat162float(h));
}
__device__ __forceinline__ void ldsm4(uint& r0, uint& r1, uint& r2, uint& r3, uint addr) {
    asm volatile("ldmatrix.sync.aligned.m8n8.x4.shared.b16 {%0,%1,%2,%3}, [%4];"
                 : "=r"(r0), "=r"(r1), "=r"(r2), "=r"(r3) : "r"(addr));
}
__device__ __forceinline__ void ldsm4t(uint& r0, uint& r1, uint& r2, uint& r3, uint addr) {
    asm volatile("ldmatrix.sync.aligned.m8n8.x4.trans.shared.b16 {%0,%1,%2,%3}, [%4];"
                 : "=r"(r0), "=r"(r1), "=r"(r2), "=r"(r3) : "r"(addr));
}
__device__ __forceinline__ void mma_bf16(float* c, const uint* a, uint b0, uint b1) {
    asm volatile("mma.sync.aligned.m16n8k16.row.col.f32.bf16.bf16.f32 "
                 "{%0,%1,%2,%3},{%4,%5,%6,%7},{%8,%9},{%0,%1,%2,%3};"
                 : "+f"(c[0]), "+f"(c[1]), "+f"(c[2]), "+f"(c[3])
                 : "r"(a[0]), "r"(a[1]), "r"(a[2]), "r"(a[3]), "r"(b0), "r"(b1));
}
__device__ __forceinline__ void cp16(uint dst, const void* src) {
    asm volatile("cp.async.cg.shared.global [%0], [%1], 16;" :: "r"(dst), "l"(src));
}
__device__ __forceinline__ void cp16z(uint dst, const void* src, uint sz) {
    asm volatile("cp.async.cg.shared.global [%0], [%1], 16, %2;" :: "r"(dst), "l"(src), "r"(sz));
}
__device__ __forceinline__ void cp_commit() { asm volatile("cp.async.commit_group;"); }

// ---------------- CSR build ----------------------------------------------------
__global__ void k_init() {
    int i = blockIdx.x * blockDim.x + threadIdx.x;
    if (i < NN) { g_deg[i] = 0; g_cur[i] = 0; }
}
__global__ void k_hist(const int* __restrict__ dst) {
    int e = blockIdx.x * blockDim.x + threadIdx.x;
    if (e < NE) atomicAdd(&g_deg[dst[e]], 1);
}
__global__ __launch_bounds__(256) void k_scan_part() {
    __shared__ int ws[8];
    int b = blockIdx.x, tid = threadIdx.x;
    int lane = tid & 31, wid = tid >> 5;
    int i = b * 256 + tid;
    int x = (i < NN) ? g_deg[i] : 0;
    int v = x;
    #pragma unroll
    for (int o = 1; o < 32; o <<= 1) {
        int y = __shfl_up_sync(0xffffffffu, v, o);
        if (lane >= o) v += y;
    }
    if (lane == 31) ws[wid] = v;
    __syncthreads();
    if (tid < 8) {
        int w = ws[tid];
        #pragma unroll
        for (int o = 1; o < 8; o <<= 1) {
            int y = __shfl_up_sync(0xffu, w, o);
            if (tid >= o) w += y;
        }
        ws[tid] = w;
    }
    __syncthreads();
    int add = wid ? ws[wid - 1] : 0;
    if (i < NN) g_off[i] = add + v - x;
    if (tid == 255) g_bt[b] = add + v;
}
__global__ void k_scan_top() {
    int tid = threadIdx.x;
    int v = (tid < 40) ? g_bt[tid] : 0;
    int e = v;
    #pragma unroll
    for (int o = 1; o < 64; o <<= 1) {
        int y = __shfl_up_sync(0xffffffffu, e, o);
        if ((threadIdx.x & 31) >= o) e += y;
    }
    __shared__ int carry;
    if (tid == 31) carry = e;
    __syncthreads();
    if (tid < 40) {
        int ex = e - v + ((tid >= 32) ? carry : 0);
        g_bt[tid] = ex;
    }
    if (tid == 0) g_off[NN] = NE;
}
__global__ __launch_bounds__(256) void k_scan_add() {
    int b = blockIdx.x;
    int i = b * 256 + threadIdx.x;
    if (b > 0 && i < NN) g_off[i] += g_bt[b];
}
__global__ void k_scatter(const int* __restrict__ src, const int* __restrict__ dst) {
    int e = blockIdx.x * blockDim.x + threadIdx.x;
    if (e < NE) {
        int d = dst[e];
        int pos = g_off[d] + atomicAdd(&g_cur[d], 1);
        g_srcs[pos] = src[e];
    }
}

// ---------------- fused fp32 -> bf16 hi/lo, vectorized x4 ------------------------
__global__ void k_cvt2(const float4* __restrict__ a4, bf16* __restrict__ ah,
                       bf16* __restrict__ al, int na4,
                       const float4* __restrict__ b4, bf16* __restrict__ bh,
                       bf16* __restrict__ bl, int nb4) {
    int i = blockIdx.x * blockDim.x + threadIdx.x;
    if (i < na4) {
        float4 v = a4[i];
        bf16 h4[4], l4[4];
        f32split(v.x, h4[0], l4[0]); f32split(v.y, h4[1], l4[1]);
        f32split(v.z, h4[2], l4[2]); f32split(v.w, h4[3], l4[3]);
        *(uint2*)(ah + i * 4) = *(uint2*)h4;
        *(uint2*)(al + i * 4) = *(uint2*)l4;
    } else if (i < na4 + nb4) {
        int j = i - na4;
        float4 v = b4[j];
        bf16 h4[4], l4[4];
        f32split(v.x, h4[0], l4[0]); f32split(v.y, h4[1], l4[1]);
        f32split(v.z, h4[2], l4[2]); f32split(v.w, h4[3], l4[3]);
        *(uint2*)(bh + j * 4) = *(uint2*)h4;
        *(uint2*)(bl + j * 4) = *(uint2*)l4;
    }
}

// ---------------- weight folding (bf16-hi outputs) -------------------------------
__global__ __launch_bounds__(256) void k_small(
    const float* __restrict__ wq, const float* __restrict__ wk,
    const float* __restrict__ wv, const float* __restrict__ wp,
    bf16* __restrict__ pMh, bf16* __restrict__ pWh)
{
    int z = blockIdx.z;
    const float* A; const float* B; bf16* Ch; int tb;
    if (z < 3) { A = wq + z * DD * DD; B = wk + z * DD * DD;
                 Ch = pMh + z * DD * DD; tb = 1; }
    else       { A = wv + (z - 3) * DD * DD; B = wp + (z - 3) * DD * DD;
                 Ch = pWh + (z - 3) * DD * DD; tb = 0; }

    __shared__ float As[16][65];
    __shared__ float Bs[16][65];
    int tid = threadIdx.x;
    int tx = tid & 15, ty = tid >> 4;
    int row0 = blockIdx.y * 64, col0 = blockIdx.x * 64;
    float acc[4][4] = {};

    for (int kt = 0; kt < DD; kt += 16) {
        {
            int r = tid >> 2, c = (tid & 3) * 4;
            float4 v = *(const float4*)(A + (row0 + r) * DD + kt + c);
            As[c + 0][r] = v.x; As[c + 1][r] = v.y; As[c + 2][r] = v.z; As[c + 3][r] = v.w;
        }
        if (tb) {
            int c = tid >> 2, k = (tid & 3) * 4;
            float4 v = *(const float4*)(B + (col0 + c) * DD + kt + k);
            Bs[k + 0][c] = v.x; Bs[k + 1][c] = v.y; Bs[k + 2][c] = v.z; Bs[k + 3][c] = v.w;
        } else {
            int k = tid >> 4, c = (tid & 15) * 4;
            float4 v = *(const float4*)(B + (kt + k) * DD + col0 + c);
            Bs[k][c + 0] = v.x; Bs[k][c + 1] = v.y; Bs[k][c + 2] = v.z; Bs[k][c + 3] = v.w;
        }
        __syncthreads();
        #pragma unroll
        for (int kk = 0; kk < 16; kk++) {
            float a[4], b[4];
            #pragma unroll
            for (int i = 0; i < 4; i++) { a[i] = As[kk][ty * 4 + i]; b[i] = Bs[kk][tx * 4 + i]; }
            #pragma unroll
            for (int i = 0; i < 4; i++)
                #pragma unroll
                for (int j = 0; j < 4; j++)
                    acc[i][j] += a[i] * b[j];
        }
        __syncthreads();
    }
    #pragma unroll
    for (int i = 0; i < 4; i++)
        #pragma unroll
        for (int j = 0; j < 4; j++)
            Ch[(row0 + ty * 4 + i) * DD + col0 + tx * 4 + j] = __float2bfloat16(acc[i][j]);
}

// ---------------- h0 GEMM: 64x128 tile, 3 products, occ 2 -----------------------
#define STH_ELEMS 13824
#define A_PITCH 40
#define B_PITCH 136

__global__ __launch_bounds__(256, 2) void k_mma_h0(
    const bf16* __restrict__ Ah, const bf16* __restrict__ Al,
    const bf16* __restrict__ Bh, const bf16* __restrict__ Bl,
    const float* __restrict__ bias,
    bf16* __restrict__ Chi, bf16* __restrict__ Clo)
{
    extern __shared__ __align__(16) bf16 smem[];
    int tid = threadIdx.x;
    int lane = tid & 31, warp = tid >> 5;
    int wm = warp & 1, wn = warp >> 1;
    int row0 = blockIdx.y * 64, col0 = blockIdx.x * 128;

    uint sbase = (uint)__cvta_generic_to_shared(smem);
    int a_r0 = tid >> 2,        a_c0 = (tid & 3) * 8;
    int b_r0 = tid >> 4,        b_c0 = (tid & 15) * 8;
    int b_r1 = (tid + 256) >> 4;

    int ga0 = row0 + a_r0;
    uint sz0 = (ga0 < NN) ? 16u : 0u;
    int ca0 = (ga0 < NN) ? ga0 : 0;

    auto issue = [&](int st, int kt) {
        uint base = sbase + (uint)(st * STH_ELEMS) * 2u;
        uint dA0 = base + (uint)(a_r0 * A_PITCH + a_c0) * 2u;
        cp16z(dA0,            Ah + (size_t)ca0 * DD + kt + a_c0, sz0);
        cp16z(dA0 + 2560u*2u, Al + (size_t)ca0 * DD + kt + a_c0, sz0);
        uint dB0 = base + (5120u + (uint)(b_r0 * B_PITCH + b_c0)) * 2u;
        uint dB1 = base + (5120u + (uint)(b_r1 * B_PITCH + b_c0)) * 2u;
        cp16(dB0, Bh + (size_t)(kt + b_r0) * DD + col0 + b_c0);
        cp16(dB1, Bh + (size_t)(kt + b_r1) * DD + col0 + b_c0);
        cp16(dB0 + 4352u*2u, Bl + (size_t)(kt + b_r0) * DD + col0 + b_c0);
        cp16(dB1 + 4352u*2u, Bl + (size_t)(kt + b_r1) * DD + col0 + b_c0);
    };

    float acc[2][4][4] = {};
    issue(0, 0);   cp_commit();
    issue(1, 32);  cp_commit();

    #pragma unroll
    for (int i = 0; i < 8; i++) {
        if (i < 7) asm volatile("cp.async.wait_group 1;");
        else       asm volatile("cp.async.wait_group 0;");
        __syncthreads();
        if (i < 6) { issue((i + 2) % 3, (i + 2) * 32); cp_commit(); }

        int st = i % 3;
        uint base = sbase + (uint)(st * STH_ELEMS) * 2u;
        uint aAh = base, aAl = base + 2560u * 2u;
        uint aBh = base + 5120u * 2u, aBl = base + 9472u * 2u;

        #pragma unroll
        for (int ks = 0; ks < 32; ks += 16) {
            int arow = lane & 15;
            int kcol = ks + ((lane >> 4) << 3);
            uint ah[2][4], al[2][4];
            #pragma unroll
            for (int mi = 0; mi < 2; mi++) {
                uint off = (uint)((wm * 32 + mi * 16 + arow) * A_PITCH + kcol) * 2u;
                ldsm4(ah[mi][0], ah[mi][1], ah[mi][2], ah[mi][3], aAh + off);
                ldsm4(al[mi][0], al[mi][1], al[mi][2], al[mi][3], aAl + off);
            }
            uint bhf[2][4], blf[2][4];
            int brow = ks + (lane & 15);
            #pragma unroll
            for (int ng = 0; ng < 2; ng++) {
                int bcol = wn * 32 + ng * 16 + ((lane >> 4) << 3);
                uint off = (uint)(brow * B_PITCH + bcol) * 2u;
                ldsm4t(bhf[ng][0], bhf[ng][1], bhf[ng][2], bhf[ng][3], aBh + off);
                ldsm4t(blf[ng][0], blf[ng][1], blf[ng][2], blf[ng][3], aBl + off);
            }
            #pragma unroll
            for (int mi = 0; mi < 2; mi++)
                #pragma unroll
                for (int ng = 0; ng < 2; ng++) {
                    mma_bf16(acc[mi][ng * 2],     ah[mi], bhf[ng][0], bhf[ng][1]);
                    mma_bf16(acc[mi][ng * 2 + 1], ah[mi], bhf[ng][2], bhf[ng][3]);
                }
            #pragma unroll
            for (int mi = 0; mi < 2; mi++)
                #pragma unroll
                for (int ng = 0; ng < 2; ng++) {
                    mma_bf16(acc[mi][ng * 2],     al[mi], bhf[ng][0], bhf[ng][1]);
                    mma_bf16(acc[mi][ng * 2 + 1], al[mi], bhf[ng][2], bhf[ng][3]);
                }
            #pragma unroll
            for (int mi = 0; mi < 2; mi++)
                #pragma unroll
                for (int ng = 0; ng < 2; ng++) {
                    mma_bf16(acc[mi][ng * 2],     ah[mi], blf[ng][0], blf[ng][1]);
                    mma_bf16(acc[mi][ng * 2 + 1], ah[mi], blf[ng][2], blf[ng][3]);
                }
        }
    }

    int grp = lane >> 2, q = lane & 3;
    #pragma unroll
    for (int mi = 0; mi < 2; mi++) {
        int rb = row0 + wm * 32 + mi * 16 + grp;
        #pragma unroll
        for (int nj = 0; nj < 4; nj++) {
            int cb = col0 + wn * 32 + nj * 8 + q * 2;
            float b0 = bias[cb], b1 = bias[cb + 1];
            float v0 = fmaxf(acc[mi][nj][0] + b0, 0.f);
            float v1 = fmaxf(acc[mi][nj][1] + b1, 0.f);
            float v2 = fmaxf(acc[mi][nj][2] + b0, 0.f);
            float v3 = fmaxf(acc[mi][nj][3] + b1, 0.f);
            if (rb < NN) {
                size_t o = (size_t)rb * DD + cb;
                bf16 h0, l0, h1, l1;
                f32split(v0, h0, l0); f32split(v1, h1, l1);
                Chi[o] = h0; Chi[o + 1] = h1;
                Clo[o] = l0; Clo[o + 1] = l1;
            }
            if (rb + 8 < NN) {
                size_t o = (size_t)(rb + 8) * DD + cb;
                bf16 h2, l2, h3, l3;
                f32split(v2, h2, l2); f32split(v3, h3, l3);
                Chi[o] = h2; Chi[o + 1] = h3;
                Clo[o] = l2; Clo[o + 1] = l3;
            }
        }
    }
}

// ---------------- unified 2-product GEMM, 64x128 tile, K32, occ 3 ---------------
#define STG_ELEMS 9472

__global__ __launch_bounds__(256, 3) void k_gemm(
    const bf16* __restrict__ Ah, const bf16* __restrict__ Al,
    const bf16* __restrict__ Bh,
    float* __restrict__ f32_out, const float* __restrict__ bias,
    const bf16* __restrict__ rhh, const bf16* __restrict__ rhl,
    bf16* __restrict__ Chi, bf16* __restrict__ Clo, int row_base)
{
    extern __shared__ __align__(16) bf16 smem[];
    int col0 = blockIdx.x * 128;
    int row0 = row_base + blockIdx.y * 64;

    int tid = threadIdx.x;
    int lane = tid & 31, warp = tid >> 5;
    int wm = warp & 1, wn = warp >> 1;

    uint sbase = (uint)__cvta_generic_to_shared(smem);
    int a_r0 = tid >> 2,        a_c0 = (tid & 3) * 8;
    int b_r0 = tid >> 4,        b_c0 = (tid & 15) * 8;
    int b_r1 = (tid + 256) >> 4;

    int ga0 = row0 + a_r0;
    uint sz0 = (ga0 < NN) ? 16u : 0u;
    int ca0 = (ga0 < NN) ? ga0 : 0;

    auto issue = [&](int st, int kt) {
        uint base = sbase + (uint)(st * STG_ELEMS) * 2u;
        uint dA0 = base + (uint)(a_r0 * A_PITCH + a_c0) * 2u;
        cp16z(dA0,            Ah + (size_t)ca0 * DD + kt + a_c0, sz0);
        cp16z(dA0 + 2560u*2u, Al + (size_t)ca0 * DD + kt + a_c0, sz0);
        uint dB0 = base + (5120u + (uint)(b_r0 * B_PITCH + b_c0)) * 2u;
        uint dB1 = base + (5120u + (uint)(b_r1 * B_PITCH + b_c0)) * 2u;
        cp16(dB0, Bh + (size_t)(kt + b_r0) * DD + col0 + b_c0);
        cp16(dB1, Bh + (size_t)(kt + b_r1) * DD + col0 + b_c0);
    };

    float acc[2][4][4] = {};
    issue(0, 0);   cp_commit();
    issue(1, 32);  cp_commit();

    #pragma unroll
    for (int i = 0; i < 8; i++) {
        if (i < 7) asm volatile("cp.async.wait_group 1;");
        else       asm volatile("cp.async.wait_group 0;");
        __syncthreads();
        if (i < 6) { issue((i + 2) % 3, (i + 2) * 32); cp_commit(); }

        int st = i % 3;
        uint base = sbase + (uint)(st * STG_ELEMS) * 2u;
        uint aAh = base, aAl = base + 2560u * 2u;
        uint aBh = base + 5120u * 2u;

        #pragma unroll
        for (int ks = 0; ks < 32; ks += 16) {
            int arow = lane & 15;
            int kcol = ks + ((lane >> 4) << 3);
            uint ah[2][4], al[2][4];
            #pragma unroll
            for (int mi = 0; mi < 2; mi++) {
                uint off = (uint)((wm * 32 + mi * 16 + arow) * A_PITCH + kcol) * 2u;
                ldsm4(ah[mi][0], ah[mi][1], ah[mi][2], ah[mi][3], aAh + off);
                ldsm4(al[mi][0], al[mi][1], al[mi][2], al[mi][3], aAl + off);
            }
            uint bhf[2][4];
            int brow = ks + (lane & 15);
            #pragma unroll
            for (int ng = 0; ng < 2; ng++) {
                int bcol = wn * 32 + ng * 16 + ((lane >> 4) << 3);
                uint off = (uint)(brow * B_PITCH + bcol) * 2u;
                ldsm4t(bhf[ng][0], bhf[ng][1], bhf[ng][2], bhf[ng][3], aBh + off);
            }
            #pragma unroll
            for (int mi = 0; mi < 2; mi++)
                #pragma unroll
                for (int ng = 0; ng < 2; ng++) {
                    mma_bf16(acc[mi][ng * 2],     ah[mi], bhf[ng][0], bhf[ng][1]);
                    mma_bf16(acc[mi][ng * 2 + 1], ah[mi], bhf[ng][2], bhf[ng][3]);
                }
            #pragma unroll
            for (int mi = 0; mi < 2; mi++)
                #pragma unroll
                for (int ng = 0; ng < 2; ng++) {
                    mma_bf16(acc[mi][ng * 2],     al[mi], bhf[ng][0], bhf[ng][1]);
                    mma_bf16(acc[mi][ng * 2 + 1], al[mi], bhf[ng][2], bhf[ng][3]);
                }
        }
    }

    int grp = lane >> 2, q = lane & 3;
    #pragma unroll
    for (int mi = 0; mi < 2; mi++) {
        int rb = row0 + wm * 32 + mi * 16 + grp;
        #pragma unroll
        for (int nj = 0; nj < 4; nj++) {
            int cb = col0 + wn * 32 + nj * 8 + q * 2;
            float v0 = acc[mi][nj][0], v1 = acc[mi][nj][1];
            float v2 = acc[mi][nj][2], v3 = acc[mi][nj][3];
            if (bias) {
                float b0 = bias[cb], b1 = bias[cb + 1];
                size_t o0 = (size_t)rb * DD + cb;
                size_t o1 = (size_t)(rb + 8) * DD + cb;
                float r00 = 0.f, r01 = 0.f, r10 = 0.f, r11 = 0.f;
                if (rb < NN) {
                    float2 a2 = __bfloat1622float2(*(const __nv_bfloat162*)(rhh + o0));
                    float2 b2 = __bfloat1622float2(*(const __nv_bfloat162*)(rhl + o0));
                    r00 = a2.x + b2.x; r01 = a2.y + b2.y;
                }
                if (rb + 8 < NN) {
                    float2 a2 = __bfloat1622float2(*(const __nv_bfloat162*)(rhh + o1));
                    float2 b2 = __bfloat1622float2(*(const __nv_bfloat162*)(rhl + o1));
                    r10 = a2.x + b2.x; r11 = a2.y + b2.y;
                }
                v0 = fmaxf(v0 + b0 + r00, 0.f);
                v1 = fmaxf(v1 + b1 + r01, 0.f);
                v2 = fmaxf(v2 + b0 + r10, 0.f);
                v3 = fmaxf(v3 + b1 + r11, 0.f);
            }
            if (rb < NN) {
                size_t o = (size_t)rb * DD + cb;
                if (f32_out) { f32_out[o] = v0; f32_out[o + 1] = v1; }
                if (Chi) {
                    bf16 h0, l0, h1, l1;
                    f32split(v0, h0, l0); f32split(v1, h1, l1);
                    Chi[o] = h0; Chi[o + 1] = h1;
                    Clo[o] = l0; Clo[o + 1] = l1;
                }
            }
            if (rb + 8 < NN) {
                size_t o = (size_t)(rb + 8) * DD + cb;
                if (f32_out) { f32_out[o] = v2; f32_out[o + 1] = v3; }
                if (Chi) {
                    bf16 h2, l2, h3, l3;
                    f32split(v2, h2, l2); f32split(v3, h3, l3);
                    Chi[o] = h2; Chi[o + 1] = h3;
                    Clo[o] = l2; Clo[o + 1] = l3;
                }
            }
        }
    }
}

// ---------------- per-node online-softmax h-aggregation -------------------------
__global__ __launch_bounds__(256) void k_edge(
    const bf16* __restrict__ hhin,
    bf16* __restrict__ agg_hi, bf16* __restrict__ agg_lo,
    int n_base, int n_count)
{
    int gw = (blockIdx.x * blockDim.x + threadIdx.x) >> 5;
    int lane = threadIdx.x & 31;
    if (gw >= n_count) return;
    int n = n_base + gw;
    int c0 = lane * 8;

    float t8[8];
    *(float4*)&t8[0] = *(const float4*)(g_t + (size_t)n * DD + c0);
    *(float4*)&t8[4] = *(const float4*)(g_t + (size_t)n * DD + c0 + 4);

    float m = -INFINITY, s = 0.f;
    float acc[8] = {};

    int e0 = g_off[n], e1 = g_off[n + 1];
    uint4 hv0, hv1;
    if (e0 < e1) {
        int sN = g_srcs[e0];
        hv0 = *(const uint4*)(hhin + (size_t)sN * DD + c0);
    }
    if (e0 + 1 < e1) {
        int sN = g_srcs[e0 + 1];
        hv1 = *(const uint4*)(hhin + (size_t)sN * DD + c0);
    }
    for (int e = e0; e < e1; e++) {
        uint4 hv = hv0;
        hv0 = hv1;
        if (e + 2 < e1) {
            int sN = g_srcs[e + 2];
            hv1 = *(const uint4*)(hhin + (size_t)sN * DD + c0);
        }

        const __nv_bfloat162* hp = (const __nv_bfloat162*)&hv;
        float hf[8];
        #pragma unroll
        for (int j = 0; j < 4; j++) {
            float2 f = __bfloat1622float2(hp[j]);
            hf[2 * j] = f.x; hf[2 * j + 1] = f.y;
        }
        float d = 0.f;
        #pragma unroll
        for (int j = 0; j < 8; j++) d += t8[j] * hf[j];
        #pragma unroll
        for (int o = 16; o > 0; o >>= 1) d += __shfl_xor_sync(0xffffffffu, d, o);
        d *= 0.0625f;

        float nm = fmaxf(m, d);
        float c = __expf(m - nm);
        float w = __expf(d - nm);
        s = s * c + w;
        m = nm;

        #pragma unroll
        for (int j = 0; j < 8; j++)
            acc[j] = acc[j] * c + w * hf[j];
    }

    float inv = 1.0f / (s + 1e-9f);
    bf16 hh8[8], hl8[8];
    #pragma unroll
    for (int j = 0; j < 8; j++) f32split(acc[j] * inv, hh8[j], hl8[j]);
    *(uint4*)(agg_hi + (size_t)n * DD + c0) = *(uint4*)&hh8[0];
    *(uint4*)(agg_lo + (size_t)n * DD + c0) = *(uint4*)&hl8[0];
}

// ---------------- launch ----------------------------------------------------------
extern "C" void kernel_launch(void* const* d_in, const int* in_sizes, int n_in,
                              void* d_out, int out_size)
{
    const float* x    = (const float*)d_in[0];
    const int*   edges= (const int*)  d_in[1];
    const float* w_in = (const float*)d_in[2];
    const float* b_in = (const float*)d_in[3];
    const float* wq   = (const float*)d_in[4];
    const float* wk   = (const float*)d_in[5];
    const float* wv   = (const float*)d_in[6];
    const float* wp   = (const float*)d_in[7];
    const float* bp   = (const float*)d_in[8];
    float* out = (float*)d_out;

    const int* src = edges;
    const int* dst = edges + NE;

    float *pt;
    bf16 *pxh, *pxl, *phhA, *phlA, *phhB, *phlB, *pwinh, *pwinl, *pMh, *pWh;
    cudaGetSymbolAddress((void**)&pt,    g_t);
    cudaGetSymbolAddress((void**)&pxh,   g_xh);
    cudaGetSymbolAddress((void**)&pxl,   g_xl);
    cudaGetSymbolAddress((void**)&phhA,  g_hhA);
    cudaGetSymbolAddress((void**)&phlA,  g_hlA);
    cudaGetSymbolAddress((void**)&phhB,  g_hhB);
    cudaGetSymbolAddress((void**)&phlB,  g_hlB);
    cudaGetSymbolAddress((void**)&pwinh, g_winh);
    cudaGetSymbolAddress((void**)&pwinl, g_winl);
    cudaGetSymbolAddress((void**)&pMh,   g_Mh);
    cudaGetSymbolAddress((void**)&pWh,   g_Wh);

    static cudaStream_t s_side = nullptr, s_b = nullptr;
    static cudaEvent_t s_ev0 = nullptr, s_evFold = nullptr, s_evCsr = nullptr;
    static cudaEvent_t s_evH0 = nullptr;
    static cudaEvent_t s_evA[NL], s_evB[NL];
    if (!s_side) {
        cudaFuncSetAttribute(k_mma_h0, cudaFuncAttributeMaxDynamicSharedMemorySize,
                             3 * STH_ELEMS * 2);
        cudaFuncSetAttribute(k_gemm, cudaFuncAttributeMaxDynamicSharedMemorySize,
                             3 * STG_ELEMS * 2);
        cudaStreamCreateWithFlags(&s_side, cudaStreamNonBlocking);
        cudaStreamCreateWithFlags(&s_b, cudaStreamNonBlocking);
        cudaEventCreateWithFlags(&s_ev0, cudaEventDisableTiming);
        cudaEventCreateWithFlags(&s_evFold, cudaEventDisableTiming);
        cudaEventCreateWithFlags(&s_evCsr, cudaEventDisableTiming);
        cudaEventCreateWithFlags(&s_evH0, cudaEventDisableTiming);
        for (int l = 0; l < NL; l++) {
            cudaEventCreateWithFlags(&s_evA[l], cudaEventDisableTiming);
            cudaEventCreateWithFlags(&s_evB[l], cudaEventDisableTiming);
        }
    }

    const int ROWS_A = RSPLIT;            // 5056 = 79*64
    const int ROWS_B = NN - RSPLIT;       // 4944
    dim3 gwA(2, 79), gwB(2, 78);          // 78*64=4992 >= 4944

    // ---- fork: weight folding + CSR on side stream
    cudaEventRecord(s_ev0, 0);
    cudaStreamWaitEvent(s_side, s_ev0, 0);
    cudaStreamWaitEvent(s_b, s_ev0, 0);
    k_small    <<<dim3(4, 4, 6), 256, 0, s_side>>>(wq, wk, wv, wp, pMh, pWh);
    cudaEventRecord(s_evFold, s_side);
    k_init     <<<(NN + 255) / 256, 256, 0, s_side>>>();
    k_hist     <<<(NE + 255) / 256, 256, 0, s_side>>>(dst);
    k_scan_part<<<40, 256, 0, s_side>>>();
    k_scan_top <<<1, 64, 0, s_side>>>();
    k_scan_add <<<40, 256, 0, s_side>>>();
    k_scatter  <<<(NE + 255) / 256, 256, 0, s_side>>>(src, dst);
    cudaEventRecord(s_evCsr, s_side);

    // ---- main stream: conversions + h0 GEMM (full width)
    int na4 = NN * DD / 4, nb4 = DD * DD / 4;
    k_cvt2<<<(na4 + nb4 + 255) / 256, 256>>>(
        (const float4*)x, pxh, pxl, na4,
        (const float4*)w_in, pwinh, pwinl, nb4);
    k_mma_h0<<<dim3(2, 157), 256, 3 * STH_ELEMS * 2>>>(
        pxh, pxl, pwinh, pwinl, b_in, phhA, phlA);
    cudaEventRecord(s_evH0, 0);

    // chain setup: stream0 = rows [0,RSPLIT), s_b = rows [RSPLIT,NN)
    cudaStreamWaitEvent(0,   s_evFold, 0);
    cudaStreamWaitEvent(s_b, s_evFold, 0);
    cudaStreamWaitEvent(s_b, s_evH0, 0);

    bf16* paggh = pxh;
    bf16* paggl = pxl;

    bf16* chh = phhA; bf16* chl = phlA;
    bf16* nhh = phhB; bf16* nhl = phlB;
    for (int l = 0; l < NL; l++) {
        // ---- t GEMMs (each chain needs only its own h rows)
        k_gemm<<<gwA, 256, 3 * STG_ELEMS * 2, 0>>>(
            chh, chl, pMh + l * DD * DD, pt,
            nullptr, nullptr, nullptr, nullptr, nullptr, 0);
        k_gemm<<<gwB, 256, 3 * STG_ELEMS * 2, s_b>>>(
            chh, chl, pMh + l * DD * DD, pt,
            nullptr, nullptr, nullptr, nullptr, nullptr, RSPLIT);

        // ---- edge needs full h: cross-chain join (and CSR on layer 0)
        if (l == 0) {
            cudaStreamWaitEvent(0,   s_evCsr, 0);
            cudaStreamWaitEvent(s_b, s_evCsr, 0);
            cudaStreamWaitEvent(0,   s_evH0, 0);   // already ordered, harmless
        } else {
            cudaStreamWaitEvent(0,   s_evB[l - 1], 0);  // other chain's p done
            cudaStreamWaitEvent(s_b, s_evA[l - 1], 0);
        }
        k_edge<<<(ROWS_A * 32 + 255) / 256, 256, 0, 0>>>(
            chh, paggh, paggl, 0, ROWS_A);
        k_edge<<<(ROWS_B * 32 + 255) / 256, 256, 0, s_b>>>(
            chh, paggh, paggl, RSPLIT, ROWS_B);

        // ---- p GEMMs (row-local)
        float* ho = (l == NL - 1) ? out : nullptr;
        bf16* oh = (l == NL - 1) ? nullptr : nhh;
        bf16* ol = (l == NL - 1) ? nullptr : nhl;
        k_gemm<<<gwA, 256, 3 * STG_ELEMS * 2, 0>>>(
            paggh, paggl, pWh + l * DD * DD, ho,
            bp + l * DD, chh, chl, oh, ol, 0);
        cudaEventRecord(s_evA[l], 0);
        k_gemm<<<gwB, 256, 3 * STG_ELEMS * 2, s_b>>>(
            paggh, paggl, pWh + l * DD * DD, ho,
            bp + l * DD, chh, chl, oh, ol, RSPLIT);
        cudaEventRecord(s_evB[l], s_b);

        bf16* t1 = chh; chh = nhh; nhh = t1;
        bf16* t2 = chl; chl = nhl; nhl = t2;
    }
    // join chain B back to the origin stream before returning
    cudaStreamWaitEvent(0, s_evB[NL - 1], 0);
}

// round 17
// speedup vs baseline: 1.5669x; 1.0491x over previous
#include <cuda_runtime.h>
#include <cuda_bf16.h>
#include <stdint.h>
#include <math.h>

#define NN 10000
#define NE 320000
#define DD 256
#define NL 3

// row split: chain A = [0, 5056), chain B = [5056, 10000)
#define RSPLIT 5056

typedef __nv_bfloat16 bf16;
typedef unsigned int uint;

// ---------------- scratch -----------------------------------------------------
__device__ float g_t[NN * DD];
__device__ bf16  g_xh[NN * DD], g_xl[NN * DD];
__device__ bf16  g_hhA[NN * DD], g_hlA[NN * DD];
__device__ bf16  g_hhB[NN * DD], g_hlB[NN * DD];
__device__ bf16  g_winh[DD * DD], g_winl[DD * DD];
__device__ bf16  g_Mh[NL * DD * DD];
__device__ bf16  g_Wh[NL * DD * DD];
__device__ int   g_deg[NN];
__device__ int   g_off[NN + 1];
__device__ int   g_cur[NN];
__device__ int   g_bt[40];
__device__ int   g_srcs[NE];

// ---------------- helpers -----------------------------------------------------
__device__ __forceinline__ void f32split(float v, bf16& h, bf16& l) {
    h = __float2bfloat16(v);
    l = __float2bfloat16(v - __bfloat162float(h));
}
__device__ __forceinline__ void ldsm4(uint& r0, uint& r1, uint& r2, uint& r3, uint addr) {
    asm volatile("ldmatrix.sync.aligned.m8n8.x4.shared.b16 {%0,%1,%2,%3}, [%4];"
                 : "=r"(r0), "=r"(r1), "=r"(r2), "=r"(r3) : "r"(addr));
}
__device__ __forceinline__ void ldsm4t(uint& r0, uint& r1, uint& r2, uint& r3, uint addr) {
    asm volatile("ldmatrix.sync.aligned.m8n8.x4.trans.shared.b16 {%0,%1,%2,%3}, [%4];"
                 : "=r"(r0), "=r"(r1), "=r"(r2), "=r"(r3) : "r"(addr));
}
__device__ __forceinline__ void mma_bf16(float* c, const uint* a, uint b0, uint b1) {
    asm volatile("mma.sync.aligned.m16n8k16.row.col.f32.bf16.bf16.f32 "
                 "{%0,%1,%2,%3},{%4,%5,%6,%7},{%8,%9},{%0,%1,%2,%3};"
                 : "+f"(c[0]), "+f"(c[1]), "+f"(c[2]), "+f"(c[3])
                 : "r"(a[0]), "r"(a[1]), "r"(a[2]), "r"(a[3]), "r"(b0), "r"(b1));
}
__device__ __forceinline__ void cp16(uint dst, const void* src) {
    asm volatile("cp.async.cg.shared.global [%0], [%1], 16;" :: "r"(dst), "l"(src));
}
__device__ __forceinline__ void cp16z(uint dst, const void* src, uint sz) {
    asm volatile("cp.async.cg.shared.global [%0], [%1], 16, %2;" :: "r"(dst), "l"(src), "r"(sz));
}
__device__ __forceinline__ void cp_commit() { asm volatile("cp.async.commit_group;"); }

// ---------------- CSR build ----------------------------------------------------
__global__ void k_init() {
    int i = blockIdx.x * blockDim.x + threadIdx.x;
    if (i < NN) { g_deg[i] = 0; g_cur[i] = 0; }
}
__global__ void k_hist(const int* __restrict__ dst) {
    int e = blockIdx.x * blockDim.x + threadIdx.x;
    if (e < NE) atomicAdd(&g_deg[dst[e]], 1);
}
__global__ __launch_bounds__(256) void k_scan_part() {
    __shared__ int ws[8];
    int b = blockIdx.x, tid = threadIdx.x;
    int lane = tid & 31, wid = tid >> 5;
    int i = b * 256 + tid;
    int x = (i < NN) ? g_deg[i] : 0;
    int v = x;
    #pragma unroll
    for (int o = 1; o < 32; o <<= 1) {
        int y = __shfl_up_sync(0xffffffffu, v, o);
        if (lane >= o) v += y;
    }
    if (lane == 31) ws[wid] = v;
    __syncthreads();
    if (tid < 8) {
        int w = ws[tid];
        #pragma unroll
        for (int o = 1; o < 8; o <<= 1) {
            int y = __shfl_up_sync(0xffu, w, o);
            if (tid >= o) w += y;
        }
        ws[tid] = w;
    }
    __syncthreads();
    int add = wid ? ws[wid - 1] : 0;
    if (i < NN) g_off[i] = add + v - x;
    if (tid == 255) g_bt[b] = add + v;
}
__global__ void k_scan_top() {
    int tid = threadIdx.x;
    int v = (tid < 40) ? g_bt[tid] : 0;
    int e = v;
    #pragma unroll
    for (int o = 1; o < 64; o <<= 1) {
        int y = __shfl_up_sync(0xffffffffu, e, o);
        if ((threadIdx.x & 31) >= o) e += y;
    }
    __shared__ int carry;
    if (tid == 31) carry = e;
    __syncthreads();
    if (tid < 40) {
        int ex = e - v + ((tid >= 32) ? carry : 0);
        g_bt[tid] = ex;
    }
    if (tid == 0) g_off[NN] = NE;
}
__global__ __launch_bounds__(256) void k_scan_add() {
    int b = blockIdx.x;
    int i = b * 256 + threadIdx.x;
    if (b > 0 && i < NN) g_off[i] += g_bt[b];
}
__global__ void k_scatter(const int* __restrict__ src, const int* __restrict__ dst) {
    int e = blockIdx.x * blockDim.x + threadIdx.x;
    if (e < NE) {
        int d = dst[e];
        int pos = g_off[d] + atomicAdd(&g_cur[d], 1);
        g_srcs[pos] = src[e];
    }
}

// ---------------- fused fp32 -> bf16 hi/lo, vectorized x4 ------------------------
__global__ void k_cvt2(const float4* __restrict__ a4, bf16* __restrict__ ah,
                       bf16* __restrict__ al, int na4,
                       const float4* __restrict__ b4, bf16* __restrict__ bh,
                       bf16* __restrict__ bl, int nb4) {
    int i = blockIdx.x * blockDim.x + threadIdx.x;
    if (i < na4) {
        float4 v = a4[i];
        bf16 h4[4], l4[4];
        f32split(v.x, h4[0], l4[0]); f32split(v.y, h4[1], l4[1]);
        f32split(v.z, h4[2], l4[2]); f32split(v.w, h4[3], l4[3]);
        *(uint2*)(ah + i * 4) = *(uint2*)h4;
        *(uint2*)(al + i * 4) = *(uint2*)l4;
    } else if (i < na4 + nb4) {
        int j = i - na4;
        float4 v = b4[j];
        bf16 h4[4], l4[4];
        f32split(v.x, h4[0], l4[0]); f32split(v.y, h4[1], l4[1]);
        f32split(v.z, h4[2], l4[2]); f32split(v.w, h4[3], l4[3]);
        *(uint2*)(bh + j * 4) = *(uint2*)h4;
        *(uint2*)(bl + j * 4) = *(uint2*)l4;
    }
}

// ---------------- weight folding (bf16-hi outputs) -------------------------------
__global__ __launch_bounds__(256) void k_small(
    const float* __restrict__ wq, const float* __restrict__ wk,
    const float* __restrict__ wv, const float* __restrict__ wp,
    bf16* __restrict__ pMh, bf16* __restrict__ pWh)
{
    int z = blockIdx.z;
    const float* A; const float* B; bf16* Ch; int tb;
    if (z < 3) { A = wq + z * DD * DD; B = wk + z * DD * DD;
                 Ch = pMh + z * DD * DD; tb = 1; }
    else       { A = wv + (z - 3) * DD * DD; B = wp + (z - 3) * DD * DD;
                 Ch = pWh + (z - 3) * DD * DD; tb = 0; }

    __shared__ float As[16][65];
    __shared__ float Bs[16][65];
    int tid = threadIdx.x;
    int tx = tid & 15, ty = tid >> 4;
    int row0 = blockIdx.y * 64, col0 = blockIdx.x * 64;
    float acc[4][4] = {};

    for (int kt = 0; kt < DD; kt += 16) {
        {
            int r = tid >> 2, c = (tid & 3) * 4;
            float4 v = *(const float4*)(A + (row0 + r) * DD + kt + c);
            As[c + 0][r] = v.x; As[c + 1][r] = v.y; As[c + 2][r] = v.z; As[c + 3][r] = v.w;
        }
        if (tb) {
            int c = tid >> 2, k = (tid & 3) * 4;
            float4 v = *(const float4*)(B + (col0 + c) * DD + kt + k);
            Bs[k + 0][c] = v.x; Bs[k + 1][c] = v.y; Bs[k + 2][c] = v.z; Bs[k + 3][c] = v.w;
        } else {
            int k = tid >> 4, c = (tid & 15) * 4;
            float4 v = *(const float4*)(B + (kt + k) * DD + col0 + c);
            Bs[k][c + 0] = v.x; Bs[k][c + 1] = v.y; Bs[k][c + 2] = v.z; Bs[k][c + 3] = v.w;
        }
        __syncthreads();
        #pragma unroll
        for (int kk = 0; kk < 16; kk++) {
            float a[4], b[4];
            #pragma unroll
            for (int i = 0; i < 4; i++) { a[i] = As[kk][ty * 4 + i]; b[i] = Bs[kk][tx * 4 + i]; }
            #pragma unroll
            for (int i = 0; i < 4; i++)
                #pragma unroll
                for (int j = 0; j < 4; j++)
                    acc[i][j] += a[i] * b[j];
        }
        __syncthreads();
    }
    #pragma unroll
    for (int i = 0; i < 4; i++)
        #pragma unroll
        for (int j = 0; j < 4; j++)
            Ch[(row0 + ty * 4 + i) * DD + col0 + tx * 4 + j] = __float2bfloat16(acc[i][j]);
}

// ---------------- h0 GEMM: 64x128 tile, 3 products, occ 2 -----------------------
#define STH_ELEMS 13824
#define A_PITCH 40
#define B_PITCH 136

__global__ __launch_bounds__(256, 2) void k_mma_h0(
    const bf16* __restrict__ Ah, const bf16* __restrict__ Al,
    const bf16* __restrict__ Bh, const bf16* __restrict__ Bl,
    const float* __restrict__ bias,
    bf16* __restrict__ Chi, bf16* __restrict__ Clo)
{
    extern __shared__ __align__(16) bf16 smem[];
    int tid = threadIdx.x;
    int lane = tid & 31, warp = tid >> 5;
    int wm = warp & 1, wn = warp >> 1;
    int row0 = blockIdx.y * 64, col0 = blockIdx.x * 128;

    uint sbase = (uint)__cvta_generic_to_shared(smem);
    int a_r0 = tid >> 2,        a_c0 = (tid & 3) * 8;
    int b_r0 = tid >> 4,        b_c0 = (tid & 15) * 8;
    int b_r1 = (tid + 256) >> 4;

    int ga0 = row0 + a_r0;
    uint sz0 = (ga0 < NN) ? 16u : 0u;
    int ca0 = (ga0 < NN) ? ga0 : 0;

    auto issue = [&](int st, int kt) {
        uint base = sbase + (uint)(st * STH_ELEMS) * 2u;
        uint dA0 = base + (uint)(a_r0 * A_PITCH + a_c0) * 2u;
        cp16z(dA0,            Ah + (size_t)ca0 * DD + kt + a_c0, sz0);
        cp16z(dA0 + 2560u*2u, Al + (size_t)ca0 * DD + kt + a_c0, sz0);
        uint dB0 = base + (5120u + (uint)(b_r0 * B_PITCH + b_c0)) * 2u;
        uint dB1 = base + (5120u + (uint)(b_r1 * B_PITCH + b_c0)) * 2u;
        cp16(dB0, Bh + (size_t)(kt + b_r0) * DD + col0 + b_c0);
        cp16(dB1, Bh + (size_t)(kt + b_r1) * DD + col0 + b_c0);
        cp16(dB0 + 4352u*2u, Bl + (size_t)(kt + b_r0) * DD + col0 + b_c0);
        cp16(dB1 + 4352u*2u, Bl + (size_t)(kt + b_r1) * DD + col0 + b_c0);
    };

    float acc[2][4][4] = {};
    issue(0, 0);   cp_commit();
    issue(1, 32);  cp_commit();

    #pragma unroll
    for (int i = 0; i < 8; i++) {
        if (i < 7) asm volatile("cp.async.wait_group 1;");
        else       asm volatile("cp.async.wait_group 0;");
        __syncthreads();
        if (i < 6) { issue((i + 2) % 3, (i + 2) * 32); cp_commit(); }

        int st = i % 3;
        uint base = sbase + (uint)(st * STH_ELEMS) * 2u;
        uint aAh = base, aAl = base + 2560u * 2u;
        uint aBh = base + 5120u * 2u, aBl = base + 9472u * 2u;

        #pragma unroll
        for (int ks = 0; ks < 32; ks += 16) {
            int arow = lane & 15;
            int kcol = ks + ((lane >> 4) << 3);
            uint ah[2][4], al[2][4];
            #pragma unroll
            for (int mi = 0; mi < 2; mi++) {
                uint off = (uint)((wm * 32 + mi * 16 + arow) * A_PITCH + kcol) * 2u;
                ldsm4(ah[mi][0], ah[mi][1], ah[mi][2], ah[mi][3], aAh + off);
                ldsm4(al[mi][0], al[mi][1], al[mi][2], al[mi][3], aAl + off);
            }
            uint bhf[2][4], blf[2][4];
            int brow = ks + (lane & 15);
            #pragma unroll
            for (int ng = 0; ng < 2; ng++) {
                int bcol = wn * 32 + ng * 16 + ((lane >> 4) << 3);
                uint off = (uint)(brow * B_PITCH + bcol) * 2u;
                ldsm4t(bhf[ng][0], bhf[ng][1], bhf[ng][2], bhf[ng][3], aBh + off);
                ldsm4t(blf[ng][0], blf[ng][1], blf[ng][2], blf[ng][3], aBl + off);
            }
            #pragma unroll
            for (int mi = 0; mi < 2; mi++)
                #pragma unroll
                for (int ng = 0; ng < 2; ng++) {
                    mma_bf16(acc[mi][ng * 2],     ah[mi], bhf[ng][0], bhf[ng][1]);
                    mma_bf16(acc[mi][ng * 2 + 1], ah[mi], bhf[ng][2], bhf[ng][3]);
                }
            #pragma unroll
            for (int mi = 0; mi < 2; mi++)
                #pragma unroll
                for (int ng = 0; ng < 2; ng++) {
                    mma_bf16(acc[mi][ng * 2],     al[mi], bhf[ng][0], bhf[ng][1]);
                    mma_bf16(acc[mi][ng * 2 + 1], al[mi], bhf[ng][2], bhf[ng][3]);
                }
            #pragma unroll
            for (int mi = 0; mi < 2; mi++)
                #pragma unroll
                for (int ng = 0; ng < 2; ng++) {
                    mma_bf16(acc[mi][ng * 2],     ah[mi], blf[ng][0], blf[ng][1]);
                    mma_bf16(acc[mi][ng * 2 + 1], ah[mi], blf[ng][2], blf[ng][3]);
                }
        }
    }

    int grp = lane >> 2, q = lane & 3;
    #pragma unroll
    for (int mi = 0; mi < 2; mi++) {
        int rb = row0 + wm * 32 + mi * 16 + grp;
        #pragma unroll
        for (int nj = 0; nj < 4; nj++) {
            int cb = col0 + wn * 32 + nj * 8 + q * 2;
            float b0 = bias[cb], b1 = bias[cb + 1];
            float v0 = fmaxf(acc[mi][nj][0] + b0, 0.f);
            float v1 = fmaxf(acc[mi][nj][1] + b1, 0.f);
            float v2 = fmaxf(acc[mi][nj][2] + b0, 0.f);
            float v3 = fmaxf(acc[mi][nj][3] + b1, 0.f);
            if (rb < NN) {
                size_t o = (size_t)rb * DD + cb;
                bf16 h0, l0, h1, l1;
                f32split(v0, h0, l0); f32split(v1, h1, l1);
                Chi[o] = h0; Chi[o + 1] = h1;
                Clo[o] = l0; Clo[o + 1] = l1;
            }
            if (rb + 8 < NN) {
                size_t o = (size_t)(rb + 8) * DD + cb;
                bf16 h2, l2, h3, l3;
                f32split(v2, h2, l2); f32split(v3, h3, l3);
                Chi[o] = h2; Chi[o + 1] = h3;
                Clo[o] = l2; Clo[o + 1] = l3;
            }
        }
    }
}

// ---------------- unified 2-product GEMM, 64x128 tile, K32, occ 3 ---------------
#define STG_ELEMS 9472

__global__ __launch_bounds__(256, 3) void k_gemm(
    const bf16* __restrict__ Ah, const bf16* __restrict__ Al,
    const bf16* __restrict__ Bh,
    float* __restrict__ f32_out, const float* __restrict__ bias,
    const bf16* __restrict__ rhh, const bf16* __restrict__ rhl,
    bf16* __restrict__ Chi, bf16* __restrict__ Clo, int row_base)
{
    extern __shared__ __align__(16) bf16 smem[];
    int col0 = blockIdx.x * 128;
    int row0 = row_base + blockIdx.y * 64;

    int tid = threadIdx.x;
    int lane = tid & 31, warp = tid >> 5;
    int wm = warp & 1, wn = warp >> 1;

    uint sbase = (uint)__cvta_generic_to_shared(smem);
    int a_r0 = tid >> 2,        a_c0 = (tid & 3) * 8;
    int b_r0 = tid >> 4,        b_c0 = (tid & 15) * 8;
    int b_r1 = (tid + 256) >> 4;

    int ga0 = row0 + a_r0;
    uint sz0 = (ga0 < NN) ? 16u : 0u;
    int ca0 = (ga0 < NN) ? ga0 : 0;

    auto issue = [&](int st, int kt) {
        uint base = sbase + (uint)(st * STG_ELEMS) * 2u;
        uint dA0 = base + (uint)(a_r0 * A_PITCH + a_c0) * 2u;
        cp16z(dA0,            Ah + (size_t)ca0 * DD + kt + a_c0, sz0);
        cp16z(dA0 + 2560u*2u, Al + (size_t)ca0 * DD + kt + a_c0, sz0);
        uint dB0 = base + (5120u + (uint)(b_r0 * B_PITCH + b_c0)) * 2u;
        uint dB1 = base + (5120u + (uint)(b_r1 * B_PITCH + b_c0)) * 2u;
        cp16(dB0, Bh + (size_t)(kt + b_r0) * DD + col0 + b_c0);
        cp16(dB1, Bh + (size_t)(kt + b_r1) * DD + col0 + b_c0);
    };

    float acc[2][4][4] = {};
    issue(0, 0);   cp_commit();
    issue(1, 32);  cp_commit();

    #pragma unroll
    for (int i = 0; i < 8; i++) {
        if (i < 7) asm volatile("cp.async.wait_group 1;");
        else       asm volatile("cp.async.wait_group 0;");
        __syncthreads();
        if (i < 6) { issue((i + 2) % 3, (i + 2) * 32); cp_commit(); }

        int st = i % 3;
        uint base = sbase + (uint)(st * STG_ELEMS) * 2u;
        uint aAh = base, aAl = base + 2560u * 2u;
        uint aBh = base + 5120u * 2u;

        #pragma unroll
        for (int ks = 0; ks < 32; ks += 16) {
            int arow = lane & 15;
            int kcol = ks + ((lane >> 4) << 3);
            uint ah[2][4], al[2][4];
            #pragma unroll
            for (int mi = 0; mi < 2; mi++) {
                uint off = (uint)((wm * 32 + mi * 16 + arow) * A_PITCH + kcol) * 2u;
                ldsm4(ah[mi][0], ah[mi][1], ah[mi][2], ah[mi][3], aAh + off);
                ldsm4(al[mi][0], al[mi][1], al[mi][2], al[mi][3], aAl + off);
            }
            uint bhf[2][4];
            int brow = ks + (lane & 15);
            #pragma unroll
            for (int ng = 0; ng < 2; ng++) {
                int bcol = wn * 32 + ng * 16 + ((lane >> 4) << 3);
                uint off = (uint)(brow * B_PITCH + bcol) * 2u;
                ldsm4t(bhf[ng][0], bhf[ng][1], bhf[ng][2], bhf[ng][3], aBh + off);
            }
            #pragma unroll
            for (int mi = 0; mi < 2; mi++)
                #pragma unroll
                for (int ng = 0; ng < 2; ng++) {
                    mma_bf16(acc[mi][ng * 2],     ah[mi], bhf[ng][0], bhf[ng][1]);
                    mma_bf16(acc[mi][ng * 2 + 1], ah[mi], bhf[ng][2], bhf[ng][3]);
                }
            #pragma unroll
            for (int mi = 0; mi < 2; mi++)
                #pragma unroll
                for (int ng = 0; ng < 2; ng++) {
                    mma_bf16(acc[mi][ng * 2],     al[mi], bhf[ng][0], bhf[ng][1]);
                    mma_bf16(acc[mi][ng * 2 + 1], al[mi], bhf[ng][2], bhf[ng][3]);
                }
        }
    }

    int grp = lane >> 2, q = lane & 3;
    #pragma unroll
    for (int mi = 0; mi < 2; mi++) {
        int rb = row0 + wm * 32 + mi * 16 + grp;
        #pragma unroll
        for (int nj = 0; nj < 4; nj++) {
            int cb = col0 + wn * 32 + nj * 8 + q * 2;
            float v0 = acc[mi][nj][0], v1 = acc[mi][nj][1];
            float v2 = acc[mi][nj][2], v3 = acc[mi][nj][3];
            if (bias) {
                float b0 = bias[cb], b1 = bias[cb + 1];
                size_t o0 = (size_t)rb * DD + cb;
                size_t o1 = (size_t)(rb + 8) * DD + cb;
                float r00 = 0.f, r01 = 0.f, r10 = 0.f, r11 = 0.f;
                if (rb < NN) {
                    float2 a2 = __bfloat1622float2(*(const __nv_bfloat162*)(rhh + o0));
                    float2 b2 = __bfloat1622float2(*(const __nv_bfloat162*)(rhl + o0));
                    r00 = a2.x + b2.x; r01 = a2.y + b2.y;
                }
                if (rb + 8 < NN) {
                    float2 a2 = __bfloat1622float2(*(const __nv_bfloat162*)(rhh + o1));
                    float2 b2 = __bfloat1622float2(*(const __nv_bfloat162*)(rhl + o1));
                    r10 = a2.x + b2.x; r11 = a2.y + b2.y;
                }
                v0 = fmaxf(v0 + b0 + r00, 0.f);
                v1 = fmaxf(v1 + b1 + r01, 0.f);
                v2 = fmaxf(v2 + b0 + r10, 0.f);
                v3 = fmaxf(v3 + b1 + r11, 0.f);
            }
            if (rb < NN) {
                size_t o = (size_t)rb * DD + cb;
                if (f32_out) { f32_out[o] = v0; f32_out[o + 1] = v1; }
                if (Chi) {
                    bf16 h0, l0, h1, l1;
                    f32split(v0, h0, l0); f32split(v1, h1, l1);
                    Chi[o] = h0; Chi[o + 1] = h1;
                    Clo[o] = l0; Clo[o + 1] = l1;
                }
            }
            if (rb + 8 < NN) {
                size_t o = (size_t)(rb + 8) * DD + cb;
                if (f32_out) { f32_out[o] = v2; f32_out[o + 1] = v3; }
                if (Chi) {
                    bf16 h2, l2, h3, l3;
                    f32split(v2, h2, l2); f32split(v3, h3, l3);
                    Chi[o] = h2; Chi[o + 1] = h3;
                    Clo[o] = l2; Clo[o + 1] = l3;
                }
            }
        }
    }
}

// ---------------- per-node online-softmax h-aggregation (paired edges) ----------
__global__ __launch_bounds__(256) void k_edge(
    const bf16* __restrict__ hhin,
    bf16* __restrict__ agg_hi, bf16* __restrict__ agg_lo,
    int n_base, int n_count)
{
    int gw = (blockIdx.x * blockDim.x + threadIdx.x) >> 5;
    int lane = threadIdx.x & 31;
    if (gw >= n_count) return;
    int n = n_base + gw;
    int c0 = lane * 8;

    float t8[8];
    *(float4*)&t8[0] = *(const float4*)(g_t + (size_t)n * DD + c0);
    *(float4*)&t8[4] = *(const float4*)(g_t + (size_t)n * DD + c0 + 4);

    float m = -INFINITY, s = 0.f;
    float acc[8] = {};

    int e0 = g_off[n], e1 = g_off[n + 1];
    int e = e0;

    // pair lookahead
    uint4 hvA, hvB, hvAn, hvBn;
    if (e + 1 < e1) {
        hvA = *(const uint4*)(hhin + (size_t)g_srcs[e] * DD + c0);
        hvB = *(const uint4*)(hhin + (size_t)g_srcs[e + 1] * DD + c0);
    }
    if (e + 3 < e1) {
        hvAn = *(const uint4*)(hhin + (size_t)g_srcs[e + 2] * DD + c0);
        hvBn = *(const uint4*)(hhin + (size_t)g_srcs[e + 3] * DD + c0);
    }

    for (; e + 1 < e1; e += 2) {
        uint4 ha = hvA, hb = hvB;
        hvA = hvAn; hvB = hvBn;
        if (e + 5 < e1) {
            hvAn = *(const uint4*)(hhin + (size_t)g_srcs[e + 4] * DD + c0);
            hvBn = *(const uint4*)(hhin + (size_t)g_srcs[e + 5] * DD + c0);
        }

        const __nv_bfloat162* pa = (const __nv_bfloat162*)&ha;
        const __nv_bfloat162* pb = (const __nv_bfloat162*)&hb;
        float fa[8], fb[8];
        #pragma unroll
        for (int j = 0; j < 4; j++) {
            float2 va = __bfloat1622float2(pa[j]);
            float2 vb = __bfloat1622float2(pb[j]);
            fa[2 * j] = va.x; fa[2 * j + 1] = va.y;
            fb[2 * j] = vb.x; fb[2 * j + 1] = vb.y;
        }
        float d1 = 0.f, d2 = 0.f;
        #pragma unroll
        for (int j = 0; j < 8; j++) { d1 += t8[j] * fa[j]; d2 += t8[j] * fb[j]; }
        #pragma unroll
        for (int o = 16; o > 0; o >>= 1) {
            d1 += __shfl_xor_sync(0xffffffffu, d1, o);
            d2 += __shfl_xor_sync(0xffffffffu, d2, o);
        }
        d1 *= 0.0625f; d2 *= 0.0625f;

        float nm = fmaxf(m, fmaxf(d1, d2));
        float c  = __expf(m - nm);
        float w1 = __expf(d1 - nm);
        float w2 = __expf(d2 - nm);
        s = s * c + w1 + w2;
        m = nm;
        #pragma unroll
        for (int j = 0; j < 8; j++)
            acc[j] = acc[j] * c + w1 * fa[j] + w2 * fb[j];
    }

    if (e < e1) {  // odd tail
        uint4 hv = *(const uint4*)(hhin + (size_t)g_srcs[e] * DD + c0);
        const __nv_bfloat162* hp = (const __nv_bfloat162*)&hv;
        float hf[8];
        #pragma unroll
        for (int j = 0; j < 4; j++) {
            float2 f = __bfloat1622float2(hp[j]);
            hf[2 * j] = f.x; hf[2 * j + 1] = f.y;
        }
        float d = 0.f;
        #pragma unroll
        for (int j = 0; j < 8; j++) d += t8[j] * hf[j];
        #pragma unroll
        for (int o = 16; o > 0; o >>= 1) d += __shfl_xor_sync(0xffffffffu, d, o);
        d *= 0.0625f;

        float nm = fmaxf(m, d);
        float c = __expf(m - nm);
        float w = __expf(d - nm);
        s = s * c + w;
        m = nm;
        #pragma unroll
        for (int j = 0; j < 8; j++)
            acc[j] = acc[j] * c + w * hf[j];
    }

    float inv = 1.0f / (s + 1e-9f);
    bf16 hh8[8], hl8[8];
    #pragma unroll
    for (int j = 0; j < 8; j++) f32split(acc[j] * inv, hh8[j], hl8[j]);
    *(uint4*)(agg_hi + (size_t)n * DD + c0) = *(uint4*)&hh8[0];
    *(uint4*)(agg_lo + (size_t)n * DD + c0) = *(uint4*)&hl8[0];
}

// ---------------- launch ----------------------------------------------------------
extern "C" void kernel_launch(void* const* d_in, const int* in_sizes, int n_in,
                              void* d_out, int out_size)
{
    const float* x    = (const float*)d_in[0];
    const int*   edges= (const int*)  d_in[1];
    const float* w_in = (const float*)d_in[2];
    const float* b_in = (const float*)d_in[3];
    const float* wq   = (const float*)d_in[4];
    const float* wk   = (const float*)d_in[5];
    const float* wv   = (const float*)d_in[6];
    const float* wp   = (const float*)d_in[7];
    const float* bp   = (const float*)d_in[8];
    float* out = (float*)d_out;

    const int* src = edges;
    const int* dst = edges + NE;

    float *pt;
    bf16 *pxh, *pxl, *phhA, *phlA, *phhB, *phlB, *pwinh, *pwinl, *pMh, *pWh;
    cudaGetSymbolAddress((void**)&pt,    g_t);
    cudaGetSymbolAddress((void**)&pxh,   g_xh);
    cudaGetSymbolAddress((void**)&pxl,   g_xl);
    cudaGetSymbolAddress((void**)&phhA,  g_hhA);
    cudaGetSymbolAddress((void**)&phlA,  g_hlA);
    cudaGetSymbolAddress((void**)&phhB,  g_hhB);
    cudaGetSymbolAddress((void**)&phlB,  g_hlB);
    cudaGetSymbolAddress((void**)&pwinh, g_winh);
    cudaGetSymbolAddress((void**)&pwinl, g_winl);
    cudaGetSymbolAddress((void**)&pMh,   g_Mh);
    cudaGetSymbolAddress((void**)&pWh,   g_Wh);

    static cudaStream_t s_side = nullptr, s_b = nullptr;
    static cudaEvent_t s_ev0 = nullptr, s_evFold = nullptr, s_evCsr = nullptr;
    static cudaEvent_t s_evH0 = nullptr;
    static cudaEvent_t s_evA[NL], s_evB[NL];
    if (!s_side) {
        cudaFuncSetAttribute(k_mma_h0, cudaFuncAttributeMaxDynamicSharedMemorySize,
                             3 * STH_ELEMS * 2);
        cudaFuncSetAttribute(k_gemm, cudaFuncAttributeMaxDynamicSharedMemorySize,
                             3 * STG_ELEMS * 2);
        cudaStreamCreateWithFlags(&s_side, cudaStreamNonBlocking);
        cudaStreamCreateWithFlags(&s_b, cudaStreamNonBlocking);
        cudaEventCreateWithFlags(&s_ev0, cudaEventDisableTiming);
        cudaEventCreateWithFlags(&s_evFold, cudaEventDisableTiming);
        cudaEventCreateWithFlags(&s_evCsr, cudaEventDisableTiming);
        cudaEventCreateWithFlags(&s_evH0, cudaEventDisableTiming);
        for (int l = 0; l < NL; l++) {
            cudaEventCreateWithFlags(&s_evA[l], cudaEventDisableTiming);
            cudaEventCreateWithFlags(&s_evB[l], cudaEventDisableTiming);
        }
    }

    const int ROWS_A = RSPLIT;            // 5056 = 79*64
    const int ROWS_B = NN - RSPLIT;       // 4944
    dim3 gwA(2, 79), gwB(2, 78);

    // ---- fork: weight folding + CSR on side stream
    cudaEventRecord(s_ev0, 0);
    cudaStreamWaitEvent(s_side, s_ev0, 0);
    cudaStreamWaitEvent(s_b, s_ev0, 0);
    k_small    <<<dim3(4, 4, 6), 256, 0, s_side>>>(wq, wk, wv, wp, pMh, pWh);
    cudaEventRecord(s_evFold, s_side);
    k_init     <<<(NN + 255) / 256, 256, 0, s_side>>>();
    k_hist     <<<(NE + 255) / 256, 256, 0, s_side>>>(dst);
    k_scan_part<<<40, 256, 0, s_side>>>();
    k_scan_top <<<1, 64, 0, s_side>>>();
    k_scan_add <<<40, 256, 0, s_side>>>();
    k_scatter  <<<(NE + 255) / 256, 256, 0, s_side>>>(src, dst);
    cudaEventRecord(s_evCsr, s_side);

    // ---- main stream: conversions + h0 GEMM (full width)
    int na4 = NN * DD / 4, nb4 = DD * DD / 4;
    k_cvt2<<<(na4 + nb4 + 255) / 256, 256>>>(
        (const float4*)x, pxh, pxl, na4,
        (const float4*)w_in, pwinh, pwinl, nb4);
    k_mma_h0<<<dim3(2, 157), 256, 3 * STH_ELEMS * 2>>>(
        pxh, pxl, pwinh, pwinl, b_in, phhA, phlA);
    cudaEventRecord(s_evH0, 0);

    // chain setup: stream0 = rows [0,RSPLIT), s_b = rows [RSPLIT,NN)
    cudaStreamWaitEvent(0,   s_evFold, 0);
    cudaStreamWaitEvent(s_b, s_evFold, 0);
    cudaStreamWaitEvent(s_b, s_evH0, 0);

    bf16* paggh = pxh;
    bf16* paggl = pxl;

    bf16* chh = phhA; bf16* chl = phlA;
    bf16* nhh = phhB; bf16* nhl = phlB;
    for (int l = 0; l < NL; l++) {
        // ---- t GEMMs (row-local)
        k_gemm<<<gwA, 256, 3 * STG_ELEMS * 2, 0>>>(
            chh, chl, pMh + l * DD * DD, pt,
            nullptr, nullptr, nullptr, nullptr, nullptr, 0);
        k_gemm<<<gwB, 256, 3 * STG_ELEMS * 2, s_b>>>(
            chh, chl, pMh + l * DD * DD, pt,
            nullptr, nullptr, nullptr, nullptr, nullptr, RSPLIT);

        // ---- edge needs full h: cross-chain join (and CSR on layer 0)
        if (l == 0) {
            cudaStreamWaitEvent(0,   s_evCsr, 0);
            cudaStreamWaitEvent(s_b, s_evCsr, 0);
            cudaStreamWaitEvent(0,   s_evH0, 0);
        } else {
            cudaStreamWaitEvent(0,   s_evB[l - 1], 0);
            cudaStreamWaitEvent(s_b, s_evA[l - 1], 0);
        }
        k_edge<<<(ROWS_A * 32 + 255) / 256, 256, 0, 0>>>(
            chh, paggh, paggl, 0, ROWS_A);
        k_edge<<<(ROWS_B * 32 + 255) / 256, 256, 0, s_b>>>(
            chh, paggh, paggl, RSPLIT, ROWS_B);

        // ---- p GEMMs (row-local)
        float* ho = (l == NL - 1) ? out : nullptr;
        bf16* oh = (l == NL - 1) ? nullptr : nhh;
        bf16* ol = (l == NL - 1) ? nullptr : nhl;
        k_gemm<<<gwA, 256, 3 * STG_ELEMS * 2, 0>>>(
            paggh, paggl, pWh + l * DD * DD, ho,
            bp + l * DD, chh, chl, oh, ol, 0);
        cudaEventRecord(s_evA[l], 0);
        k_gemm<<<gwB, 256, 3 * STG_ELEMS * 2, s_b>>>(
            paggh, paggl, pWh + l * DD * DD, ho,
            bp + l * DD, chh, chl, oh, ol, RSPLIT);
        cudaEventRecord(s_evB[l], s_b);

        bf16* t1 = chh; chh = nhh; nhh = t1;
        bf16* t2 = chl; chl = nhl; nhl = t2;
    }
    // join chain B back to the origin stream before returning
    cudaStreamWaitEvent(0, s_evB[NL - 1], 0);
}